// round 2
// baseline (speedup 1.0000x reference)
#include <cuda_runtime.h>

#define NB 8
#define NP 2048
#define KNN 32
#define NSLOT 32
#define EPSBN 1e-5f
#define NEG_INF -3.402823466e38f

// ----------------- static device scratch (no runtime allocation) -----------------
__device__ float g_big[(size_t)NB*NP*NP];     // 134MB: pdist / energy / attn
__device__ int   g_idx[(size_t)NB*NP*KNN];
__device__ float g_xx[NB*NP];
__device__ float g_xs[(size_t)NB*128*NP];     // f1|f2 then running SA features
__device__ float g_cat[(size_t)NB*512*NP];
__device__ float g_pt[(size_t)NB*NP*64];      // P gathered term (point-major)
__device__ float g_qt[(size_t)NB*NP*64];      // Q center term (point-major)
__device__ float g_q[(size_t)NB*32*NP];
__device__ float g_kk[(size_t)NB*32*NP];
__device__ float g_d[(size_t)NB*128*NP];      // x - xr
__device__ float g_t[(size_t)NB*128*NP];      // Wt(x-xr)
__device__ float g_cs[NB*NP];                 // 1/(1e-6+colsum)
__device__ float g_tf[(size_t)NB*1024*NP];    // fuse pre-BN
__device__ float g_h1[(size_t)NB*512*NP];
__device__ float g_h2[(size_t)NB*256*NP];
__device__ float g_gm[NB*1024];               // relu(bn(max_n tf))
__device__ float g_w1g[NB*512];               // Wc1[:, :1024] @ g
__device__ float g_ssum[1024*NSLOT];
__device__ float g_ssq[1024*NSLOT];
__device__ float g_mean[1024];
__device__ float g_istd[1024];

__device__ __forceinline__ float* bsel(int s){
  switch(s){
    case 0: return g_big;  case 1: return g_xs;  case 2: return g_cat;
    case 4: return g_q;    case 5: return g_kk;  case 6: return g_d;
    case 7: return g_t;    case 8: return g_cs;  case 9: return g_tf;
    case 10: return g_h1;  case 11: return g_h2; case 12: return g_xx;
    case 13: return g_w1g;
  }
  return nullptr;
}

// ----------------- small utility kernels -----------------
__global__ void zero_slots_kernel(){
  int i = blockIdx.x*256 + threadIdx.x;
  if (i < 1024*NSLOT){ g_ssum[i] = 0.f; g_ssq[i] = 0.f; }
}

__global__ void bn_finalize_kernel(int C, float count){
  int c = blockIdx.x*blockDim.x + threadIdx.x;
  if (c >= C) return;
  float s1 = 0.f, s2 = 0.f;
  for (int s = 0; s < NSLOT; s++){ s1 += g_ssum[c*NSLOT+s]; s2 += g_ssq[c*NSLOT+s]; }
  float m = s1 / count;
  float var = s2 / count - m*m;
  g_mean[c] = m;
  g_istd[c] = rsqrtf(fmaxf(var, 0.f) + EPSBN);
}

// v = relu((v-mean)*istd), layout base[b*bstride + (choff+c)*NP + n]
__global__ void bn_relu_kernel(int dSel, long bstride, int C, int choff){
  float* data = bsel(dSel);
  long i = (long)blockIdx.x*blockDim.x + threadIdx.x;
  long tot = (long)NB*C*NP;
  if (i >= tot) return;
  int n = (int)(i % NP); long t = i / NP;
  int c = (int)(t % C);  int b = (int)(t / C);
  float* p = data + (long)b*bstride + (long)(choff+c)*NP + n;
  float v = (*p - g_mean[c]) * g_istd[c];
  *p = v > 0.f ? v : 0.f;
}

// ----------------- knn -----------------
__global__ void pdist1_kernel(const float* __restrict__ x){
  int row = blockIdx.x;                 // b*NP + n
  int b = row / NP, n = row % NP;
  const float* xb = x + (long)b*3*NP;
  float cx = xb[n], cy = xb[NP+n], cz = xb[2*NP+n];
  float* out = g_big + (long)row*NP;
  for (int m = threadIdx.x; m < NP; m += blockDim.x){
    float dx = xb[m]-cx, dy = xb[NP+m]-cy, dz = xb[2*NP+m]-cz;
    out[m] = -(dx*dx + dy*dy + dz*dz);
  }
}

__global__ void topk_kernel(){
  int row = blockIdx.x;                 // b*NP + n
  const float* src = g_big + (long)row*NP;
  int tid = threadIdx.x;
  float v[8];
  #pragma unroll
  for (int i = 0; i < 8; i++) v[i] = src[tid + i*256];
  __shared__ float swv[8]; __shared__ int swi[8]; __shared__ int sbi;
  int lane = tid & 31, wid = tid >> 5;
  int* idxout = g_idx + (long)row*KNN;
  for (int it = 0; it < KNN; it++){
    float bv = v[0]; int bs = 0;
    #pragma unroll
    for (int i = 1; i < 8; i++) if (v[i] > bv){ bv = v[i]; bs = i; }
    int bidx = tid + bs*256;
    #pragma unroll
    for (int off = 16; off; off >>= 1){
      float ov = __shfl_down_sync(0xffffffffu, bv, off);
      int   oi = __shfl_down_sync(0xffffffffu, bidx, off);
      if (ov > bv || (ov == bv && oi < bidx)){ bv = ov; bidx = oi; }
    }
    if (lane == 0){ swv[wid] = bv; swi[wid] = bidx; }
    __syncthreads();
    if (tid == 0){
      float mv = swv[0]; int mi = swi[0];
      #pragma unroll
      for (int w = 1; w < 8; w++)
        if (swv[w] > mv || (swv[w] == mv && swi[w] < mi)){ mv = swv[w]; mi = swi[w]; }
      sbi = mi; idxout[it] = mi;
    }
    __syncthreads();
    int w = sbi;
    if ((w & 255) == tid) v[w >> 8] = NEG_INF;
  }
}

// ----------------- edge conv -----------------
// P[o,n] = W[o,0:C] @ f[:,n];  Q[o,n] = (W[o,C:2C]-W[o,0:C]) @ f[:,n]
// stored point-major: g_pt/g_qt[(b*NP+n)*64 + o]
__global__ void edge_pq_kernel(const float* __restrict__ fext, int fSel, long fbstride,
                               int C, const float* __restrict__ W){
  const float* f = (fSel >= 0) ? bsel(fSel) : fext;
  int b = blockIdx.y;
  int n0 = blockIdx.x*32;
  const float* fb = f + (long)b*fbstride;
  __shared__ float sf[64][32];
  int nl = threadIdx.x & 31, og = threadIdx.x >> 5;
  for (int c = og; c < C; c += 8) sf[c][nl] = fb[(long)c*NP + n0 + nl];
  __syncthreads();
  #pragma unroll
  for (int j = 0; j < 8; j++){
    int o = og*8 + j;
    const float* w = W + (long)o*2*C;
    float ap = 0.f, aq = 0.f;
    for (int c = 0; c < C; c++){
      float fv = sf[c][nl];
      ap += w[c]*fv;
      aq += (w[C+c]-w[c])*fv;
    }
    long off = ((long)(b*NP + n0 + nl))*64 + o;
    g_pt[off] = ap; g_qt[off] = aq;
  }
}

// emax[o,n] = Q[o,n] + max_k P[o, idx[n,k]]; accumulate BN stats over all (o,k)
__global__ void edge_gather_kernel(int chbase){
  int row = blockIdx.x; int b = row / NP, n = row % NP;
  int o = threadIdx.x;
  __shared__ int sidx[KNN];
  if (o < KNN) sidx[o] = g_idx[(long)row*KNN + o];
  __syncthreads();
  float q = g_qt[(long)row*64 + o];
  float mx = NEG_INF, s1 = 0.f, s2 = 0.f;
  const float* pb = g_pt + (long)b*NP*64;
  #pragma unroll 4
  for (int k = 0; k < KNN; k++){
    float v = pb[(long)sidx[k]*64 + o] + q;
    mx = fmaxf(mx, v); s1 += v; s2 += v*v;
  }
  g_xs[((long)b*128 + chbase + o)*NP + n] = mx;
  int slot = row & (NSLOT-1);
  atomicAdd(&g_ssum[o*NSLOT + slot], s1);
  atomicAdd(&g_ssq[o*NSLOT + slot], s2);
}

__global__ void sqnorm_kernel(){
  int i = blockIdx.x*blockDim.x + threadIdx.x;  // b*NP+n
  if (i >= NB*NP) return;
  int b = i / NP, n = i % NP;
  const float* f = g_xs + (long)b*128*NP + n;
  float s = 0.f;
  #pragma unroll 8
  for (int c = 0; c < 64; c++){ float v = f[(long)c*NP]; s += v*v; }
  g_xx[i] = s;
}

// ----------------- SA layer helpers -----------------
__global__ void qk_kernel(const float* __restrict__ Wq, const float* __restrict__ Wk){
  int b = blockIdx.y, n0 = blockIdx.x*32;
  __shared__ float sf[128][32];
  int nl = threadIdx.x & 31, og = threadIdx.x >> 5;
  const float* xb = g_xs + (long)b*128*NP;
  for (int c = og; c < 128; c += 8) sf[c][nl] = xb[(long)c*NP + n0 + nl];
  __syncthreads();
  #pragma unroll
  for (int j = 0; j < 4; j++){
    int qi = og*4 + j;
    const float* wq = Wq + qi*128;
    const float* wk = Wk + qi*128;
    float aq = 0.f, ak = 0.f;
    for (int c = 0; c < 128; c++){
      float fv = sf[c][nl];
      aq += wq[c]*fv; ak += wk[c]*fv;
    }
    g_q [((long)b*32 + qi)*NP + n0 + nl] = aq;
    g_kk[((long)b*32 + qi)*NP + n0 + nl] = ak;
  }
}

__global__ void softmax_kernel(){
  long row = blockIdx.x;
  float* p = g_big + row*(long)NP;
  int tid = threadIdx.x;
  int lane = tid & 31, wid = tid >> 5;
  __shared__ float sred[8];
  __shared__ float sres;
  float v[8];
  #pragma unroll
  for (int i = 0; i < 8; i++) v[i] = p[tid + i*256];
  float m = v[0];
  #pragma unroll
  for (int i = 1; i < 8; i++) m = fmaxf(m, v[i]);
  #pragma unroll
  for (int off = 16; off; off >>= 1) m = fmaxf(m, __shfl_xor_sync(0xffffffffu, m, off));
  if (lane == 0) sred[wid] = m;
  __syncthreads();
  if (tid == 0){
    float t = sred[0];
    #pragma unroll
    for (int w = 1; w < 8; w++) t = fmaxf(t, sred[w]);
    sres = t;
  }
  __syncthreads();
  float bmax = sres;
  float s = 0.f;
  #pragma unroll
  for (int i = 0; i < 8; i++){ v[i] = __expf(v[i] - bmax); s += v[i]; }
  #pragma unroll
  for (int off = 16; off; off >>= 1) s += __shfl_xor_sync(0xffffffffu, s, off);
  __syncthreads();
  if (lane == 0) sred[wid] = s;
  __syncthreads();
  if (tid == 0){
    float t = 0.f;
    #pragma unroll
    for (int w = 0; w < 8; w++) t += sred[w];
    sres = t;
  }
  __syncthreads();
  float inv = 1.f / sres;
  #pragma unroll
  for (int i = 0; i < 8; i++) p[tid + i*256] = v[i]*inv;
}

__global__ void colsum_kernel(){
  int b = blockIdx.y;
  int m = blockIdx.x*256 + threadIdx.x;
  const float* a = g_big + (long)b*NP*NP + m;
  float s0 = 0.f, s1 = 0.f, s2 = 0.f, s3 = 0.f;
  for (int n = 0; n < NP; n += 4){
    s0 += a[(long)n*NP];
    s1 += a[(long)(n+1)*NP];
    s2 += a[(long)(n+2)*NP];
    s3 += a[(long)(n+3)*NP];
  }
  g_cs[b*NP + m] = 1.f / (1e-6f + (s0+s1)+(s2+s3));
}

__global__ void residual_kernel(int layer){
  long i = (long)blockIdx.x*blockDim.x + threadIdx.x;
  long tot = (long)NB*128*NP;
  if (i >= tot) return;
  int n = (int)(i % NP); long t = i / NP;
  int c = (int)(t % 128); int b = (int)(t / 128);
  float tv = g_t[((long)b*128 + c)*NP + n];
  float r = (tv - g_mean[c]) * g_istd[c];
  r = r > 0.f ? r : 0.f;
  long xi = ((long)b*128 + c)*NP + n;
  float v = g_xs[xi] + r;
  g_xs[xi] = v;
  g_cat[((long)b*512 + layer*128 + c)*NP + n] = v;
}

// ----------------- fuse / head helpers -----------------
__global__ void gmax_kernel(){
  int row = blockIdx.x;                 // b*1024 + o
  int o = row & 1023;
  const float* p = g_tf + (long)row*NP;
  float m = NEG_INF;
  for (int n = threadIdx.x; n < NP; n += 128) m = fmaxf(m, p[n]);
  #pragma unroll
  for (int off = 16; off; off >>= 1) m = fmaxf(m, __shfl_xor_sync(0xffffffffu, m, off));
  __shared__ float sw[4];
  int lane = threadIdx.x & 31, wid = threadIdx.x >> 5;
  if (lane == 0) sw[wid] = m;
  __syncthreads();
  if (threadIdx.x == 0){
    float mm = fmaxf(fmaxf(sw[0], sw[1]), fmaxf(sw[2], sw[3]));
    float v = (mm - g_mean[o]) * g_istd[o];
    g_gm[row] = v > 0.f ? v : 0.f;
  }
}

__global__ void w1g_kernel(const float* __restrict__ Wc1){
  int o = blockIdx.x*8 + (threadIdx.x >> 5);
  int lane = threadIdx.x & 31;
  const float* w = Wc1 + (long)o*1536;
  float acc[NB];
  #pragma unroll
  for (int b = 0; b < NB; b++) acc[b] = 0.f;
  for (int c = lane; c < 1024; c += 32){
    float wv = w[c];
    #pragma unroll
    for (int b = 0; b < NB; b++) acc[b] += wv * g_gm[b*1024 + c];
  }
  #pragma unroll
  for (int b = 0; b < NB; b++){
    #pragma unroll
    for (int off = 16; off; off >>= 1) acc[b] += __shfl_xor_sync(0xffffffffu, acc[b], off);
  }
  if (lane == 0){
    #pragma unroll
    for (int b = 0; b < NB; b++) g_w1g[b*512 + o] = acc[b];
  }
}

// ----------------- generic tiled SGEMM -----------------
// C[b] = op(A[b]) * B[b]; op=A^T if TRANSA (A stored [K][M] row-major).
// EPI: 0 none, 1 pdist(2*acc - xx[row] - xx[col]), 2 xr(e1[row*NP+col]-acc*e2[col]),
//      3 stats, 4 stats+row-bias(e1), 5 row-bias(e1) only.
template<int EPI, bool TRANSA>
__global__ void gemm_kernel(int M, int K,
  const float* __restrict__ Aext, int aSel, int lda, long sA,
  int bSel, int ldb, long sB,
  float* __restrict__ Cext, int cSel, int ldc, long sC,
  const float* __restrict__ e1ext, int e1Sel, long se1,
  int e2Sel, long se2)
{
  int bb = blockIdx.z;
  const float* A = ((aSel >= 0) ? bsel(aSel) : Aext) + (long)bb*sA;
  const float* B = bsel(bSel) + (long)bb*sB;
  float* C = ((cSel >= 0) ? bsel(cSel) : Cext) + (long)bb*sC;
  const float* E1 = nullptr;
  if (EPI == 1 || EPI == 2 || EPI == 4 || EPI == 5)
    E1 = ((e1Sel >= 0) ? bsel(e1Sel) : e1ext) + (long)bb*se1;
  const float* E2 = nullptr;
  if (EPI == 2) E2 = bsel(e2Sel) + (long)bb*se2;

  int tm = blockIdx.y*64, tn = blockIdx.x*64;
  __shared__ float As[16][64];
  __shared__ float Bs[16][64];
  int tid = threadIdx.x;
  int tx = tid & 15, ty = tid >> 4;
  float acc[4][4] = {};

  for (int k0 = 0; k0 < K; k0 += 16){
    if (TRANSA){
      int kk = tid >> 4, mm = (tid & 15)*4;
      *(float4*)&As[kk][mm] = *(const float4*)&A[(long)(k0+kk)*lda + tm + mm];
    } else {
      int mm = tid >> 2, kk = (tid & 3)*4;
      int row = tm + mm;
      float4 av = make_float4(0.f,0.f,0.f,0.f);
      if (row < M) av = *(const float4*)&A[(long)row*lda + k0 + kk];
      As[kk  ][mm] = av.x; As[kk+1][mm] = av.y;
      As[kk+2][mm] = av.z; As[kk+3][mm] = av.w;
    }
    {
      int kk = tid >> 4, nn = (tid & 15)*4;
      *(float4*)&Bs[kk][nn] = *(const float4*)&B[(long)(k0+kk)*ldb + tn + nn];
    }
    __syncthreads();
    #pragma unroll
    for (int kk = 0; kk < 16; kk++){
      float4 a4 = *(float4*)&As[kk][ty*4];
      float4 b4 = *(float4*)&Bs[kk][tx*4];
      float ar[4] = {a4.x, a4.y, a4.z, a4.w};
      float br[4] = {b4.x, b4.y, b4.z, b4.w};
      #pragma unroll
      for (int i = 0; i < 4; i++)
        #pragma unroll
        for (int j = 0; j < 4; j++)
          acc[i][j] += ar[i]*br[j];
    }
    __syncthreads();
  }

  int slot = (blockIdx.x + blockIdx.z) & (NSLOT-1);
  #pragma unroll
  for (int i = 0; i < 4; i++){
    int row = tm + ty*4 + i;
    bool ok = row < M;
    float bias = 0.f;
    if ((EPI == 4 || EPI == 5) && ok) bias = E1[row];
    float out[4];
    float s1 = 0.f, s2 = 0.f;
    int colb = tn + tx*4;
    #pragma unroll
    for (int j = 0; j < 4; j++){
      float v = acc[i][j];
      if (EPI == 1)      v = 2.f*v - (ok ? E1[row] : 0.f) - E1[colb+j];
      else if (EPI == 2) v = (ok ? E1[(long)row*NP + colb + j] : 0.f) - v*E2[colb+j];
      else               v += bias;
      out[j] = v;
      if (EPI == 3 || EPI == 4){ s1 += v; s2 += v*v; }
    }
    if (ok) *(float4*)&C[(long)row*ldc + colb] = make_float4(out[0],out[1],out[2],out[3]);
    if (EPI == 3 || EPI == 4){
      #pragma unroll
      for (int off = 8; off; off >>= 1){
        s1 += __shfl_xor_sync(0xffffffffu, s1, off);
        s2 += __shfl_xor_sync(0xffffffffu, s2, off);
      }
      if (tx == 0 && ok){
        atomicAdd(&g_ssum[row*NSLOT + slot], s1);
        atomicAdd(&g_ssq [row*NSLOT + slot], s2);
      }
    }
  }
}

// final output GEMM writes straight to d_out via Cext

// ----------------- host orchestration -----------------
extern "C" void kernel_launch(void* const* d_in, const int* in_sizes, int n_in,
                              void* d_out, int out_size) {
  (void)in_sizes; (void)n_in; (void)out_size;
  const float* x   = (const float*)d_in[0];
  const float* We1 = (const float*)d_in[1];
  const float* We2 = (const float*)d_in[3];
  const float* Wq  = (const float*)d_in[5];
  const float* Wk  = (const float*)d_in[6];
  const float* Wt  = (const float*)d_in[7];
  const float* Wf  = (const float*)d_in[9];
  const float* Wc1 = (const float*)d_in[11];
  const float* Wc2 = (const float*)d_in[13];
  const float* Wc3 = (const float*)d_in[15];
  const float* bc3 = (const float*)d_in[16];
  float* out = (float*)d_out;

  const long SBIG = (long)NP*NP;

  // ---- knn on xyz + edgeconv1 ----
  pdist1_kernel<<<NB*NP, 256>>>(x);
  topk_kernel<<<NB*NP, 256>>>();
  zero_slots_kernel<<<128, 256>>>();
  edge_pq_kernel<<<dim3(NP/32, NB), 256>>>(x, -1, (long)3*NP, 3, We1);
  edge_gather_kernel<<<NB*NP, 64>>>(0);
  bn_finalize_kernel<<<1, 64>>>(64, (float)((long)NB*NP*KNN));
  bn_relu_kernel<<<(NB*64*NP)/256, 256>>>(1, (long)128*NP, 64, 0);

  // ---- knn on f1 + edgeconv2 ----
  sqnorm_kernel<<<(NB*NP)/256, 256>>>();
  gemm_kernel<1, true><<<dim3(32, 32, NB), 256>>>(NP, 64,
      nullptr, 1, NP, (long)128*NP,   // A = f1 (g_xs ch 0..63), [K=64][M] via TRANSA
      1, NP, (long)128*NP,            // B = f1
      nullptr, 0, NP, SBIG,           // C = g_big
      nullptr, 12, NP, -1, 0);        // e1 = g_xx
  topk_kernel<<<NB*NP, 256>>>();
  zero_slots_kernel<<<128, 256>>>();
  edge_pq_kernel<<<dim3(NP/32, NB), 256>>>(nullptr, 1, (long)128*NP, 64, We2);
  edge_gather_kernel<<<NB*NP, 64>>>(64);
  bn_finalize_kernel<<<1, 64>>>(64, (float)((long)NB*NP*KNN));
  bn_relu_kernel<<<(NB*64*NP)/256, 256>>>(1, (long)128*NP, 64, 64);

  // ---- 4 SA layers ----
  for (int i = 0; i < 4; i++){
    qk_kernel<<<dim3(NP/32, NB), 256>>>(Wq + (long)i*32*128, Wk + (long)i*32*128);
    gemm_kernel<0, true><<<dim3(32, 32, NB), 256>>>(NP, 32,
        nullptr, 4, NP, (long)32*NP,  // A = q [32][N]
        5, NP, (long)32*NP,           // B = k [32][N]
        nullptr, 0, NP, SBIG,         // C = energy
        nullptr, -1, 0, -1, 0);
    softmax_kernel<<<NB*NP, 256>>>();
    colsum_kernel<<<dim3(NP/256, NB), 256>>>();
    gemm_kernel<2, false><<<dim3(32, 2, NB), 256>>>(128, NP,
        nullptr, 1, NP, (long)128*NP, // A = xs [128][N]
        0, NP, SBIG,                  // B = attn [N][N]
        nullptr, 6, NP, (long)128*NP, // C = d = xs - xr*inv
        nullptr, 1, (long)128*NP,     // e1 = xs
        8, NP);                       // e2 = inv colsum
    zero_slots_kernel<<<128, 256>>>();
    gemm_kernel<3, false><<<dim3(32, 2, NB), 256>>>(128, 128,
        Wt + (long)i*128*128, -1, 128, 0,
        6, NP, (long)128*NP,
        nullptr, 7, NP, (long)128*NP,
        nullptr, -1, 0, -1, 0);
    bn_finalize_kernel<<<1, 128>>>(128, (float)(NB*NP));
    residual_kernel<<<(NB*128*NP)/256, 256>>>(i);
  }

  // ---- fuse + global max ----
  zero_slots_kernel<<<128, 256>>>();
  gemm_kernel<3, false><<<dim3(32, 16, NB), 256>>>(1024, 512,
      Wf, -1, 512, 0,
      2, NP, (long)512*NP,
      nullptr, 9, NP, (long)1024*NP,
      nullptr, -1, 0, -1, 0);
  bn_finalize_kernel<<<8, 128>>>(1024, (float)(NB*NP));
  gmax_kernel<<<NB*1024, 128>>>();
  w1g_kernel<<<64, 256>>>(Wc1);

  // ---- head ----
  zero_slots_kernel<<<128, 256>>>();
  gemm_kernel<4, false><<<dim3(32, 8, NB), 256>>>(512, 512,
      Wc1 + 1024, -1, 1536, 0,
      2, NP, (long)512*NP,
      nullptr, 10, NP, (long)512*NP,
      nullptr, 13, 512,              // e1 = w1g per-(b,row) bias
      -1, 0);
  bn_finalize_kernel<<<4, 128>>>(512, (float)(NB*NP));
  bn_relu_kernel<<<(NB*512*NP)/256, 256>>>(10, (long)512*NP, 512, 0);

  zero_slots_kernel<<<128, 256>>>();
  gemm_kernel<3, false><<<dim3(32, 4, NB), 256>>>(256, 512,
      Wc2, -1, 512, 0,
      10, NP, (long)512*NP,
      nullptr, 11, NP, (long)256*NP,
      nullptr, -1, 0, -1, 0);
  bn_finalize_kernel<<<2, 128>>>(256, (float)(NB*NP));
  bn_relu_kernel<<<(NB*256*NP)/256, 256>>>(11, (long)256*NP, 256, 0);

  gemm_kernel<5, false><<<dim3(32, 1, NB), 256>>>(13, 256,
      Wc3, -1, 256, 0,
      11, NP, (long)256*NP,
      out, -1, NP, (long)13*NP,
      bc3, -1, 0,
      -1, 0);
}

// round 3
// speedup vs baseline: 1.1140x; 1.1140x over previous
#include <cuda_runtime.h>

#define NB 8
#define NP 2048
#define KNN 32
#define NSLOT 32
#define EPSBN 1e-5f
#define NEG_INF -3.402823466e38f

// ----------------- static device scratch (no runtime allocation) -----------------
__device__ float g_big[(size_t)NB*NP*NP];     // 134MB: pdist / energy / attn
__device__ int   g_idx[(size_t)NB*NP*KNN];
__device__ float g_xx[NB*NP];
__device__ float g_xs[(size_t)NB*128*NP];     // f1|f2 then running SA features
__device__ float g_cat[(size_t)NB*512*NP];
__device__ float g_pt[(size_t)NB*NP*64];      // P gathered term (point-major)
__device__ float g_qt[(size_t)NB*NP*64];      // Q center term (point-major)
__device__ float g_q[(size_t)NB*32*NP];
__device__ float g_kk[(size_t)NB*32*NP];
__device__ float g_d[(size_t)NB*128*NP];      // t pre-BN (SA layer)
__device__ float g_t[(size_t)NB*128*NP];      // y = Wt @ xs
__device__ float g_cs[NB*NP];                 // 1/(1e-6+colsum)
__device__ float g_tf[(size_t)NB*1024*NP];    // fuse pre-BN
__device__ float g_h1[(size_t)NB*512*NP];
__device__ float g_h2[(size_t)NB*256*NP];
__device__ float g_gm[NB*1024];               // relu(bn(max_n tf))
__device__ float g_w1g[NB*512];               // Wc1[:, :1024] @ g
__device__ float g_ssum[1024*NSLOT];
__device__ float g_ssq[1024*NSLOT];
__device__ float g_mean[1024];
__device__ float g_istd[1024];

__device__ __forceinline__ float* bsel(int s){
  switch(s){
    case 0: return g_big;  case 1: return g_xs;  case 2: return g_cat;
    case 4: return g_q;    case 5: return g_kk;  case 6: return g_d;
    case 7: return g_t;    case 8: return g_cs;  case 9: return g_tf;
    case 10: return g_h1;  case 11: return g_h2; case 12: return g_xx;
    case 13: return g_w1g;
  }
  return nullptr;
}

// ----------------- small utility kernels -----------------
__global__ void zero_slots_kernel(){
  int i = blockIdx.x*256 + threadIdx.x;
  if (i < 1024*NSLOT){ g_ssum[i] = 0.f; g_ssq[i] = 0.f; }
}

__global__ void bn_finalize_kernel(int C, float count){
  int c = blockIdx.x*blockDim.x + threadIdx.x;
  if (c >= C) return;
  float s1 = 0.f, s2 = 0.f;
  for (int s = 0; s < NSLOT; s++){ s1 += g_ssum[c*NSLOT+s]; s2 += g_ssq[c*NSLOT+s]; }
  float m = s1 / count;
  float var = s2 / count - m*m;
  g_mean[c] = m;
  g_istd[c] = rsqrtf(fmaxf(var, 0.f) + EPSBN);
}

// v = relu((v-mean)*istd), layout base[b*bstride + (choff+c)*NP + n]
__global__ void bn_relu_kernel(int dSel, long bstride, int C, int choff){
  float* data = bsel(dSel);
  long i = (long)blockIdx.x*blockDim.x + threadIdx.x;
  long tot = (long)NB*C*NP;
  if (i >= tot) return;
  int n = (int)(i % NP); long t = i / NP;
  int c = (int)(t % C);  int b = (int)(t / C);
  float* p = data + (long)b*bstride + (long)(choff+c)*NP + n;
  float v = (*p - g_mean[c]) * g_istd[c];
  *p = v > 0.f ? v : 0.f;
}

// ----------------- knn -----------------
__global__ void pdist1_kernel(const float* __restrict__ x){
  int row = blockIdx.x;                 // b*NP + n
  int b = row / NP, n = row % NP;
  const float* xb = x + (long)b*3*NP;
  float cx = xb[n], cy = xb[NP+n], cz = xb[2*NP+n];
  float* out = g_big + (long)row*NP;
  for (int m = threadIdx.x; m < NP; m += blockDim.x){
    float dx = xb[m]-cx, dy = xb[NP+m]-cy, dz = xb[2*NP+m]-cz;
    out[m] = -(dx*dx + dy*dy + dz*dz);
  }
}

__global__ void topk_kernel(){
  int row = blockIdx.x;                 // b*NP + n
  const float* src = g_big + (long)row*NP;
  int tid = threadIdx.x;
  float v[8];
  #pragma unroll
  for (int i = 0; i < 8; i++) v[i] = src[tid + i*256];
  __shared__ float swv[8]; __shared__ int swi[8]; __shared__ int sbi;
  int lane = tid & 31, wid = tid >> 5;
  int* idxout = g_idx + (long)row*KNN;
  for (int it = 0; it < KNN; it++){
    float bv = v[0]; int bs = 0;
    #pragma unroll
    for (int i = 1; i < 8; i++) if (v[i] > bv){ bv = v[i]; bs = i; }
    int bidx = tid + bs*256;
    #pragma unroll
    for (int off = 16; off; off >>= 1){
      float ov = __shfl_down_sync(0xffffffffu, bv, off);
      int   oi = __shfl_down_sync(0xffffffffu, bidx, off);
      if (ov > bv || (ov == bv && oi < bidx)){ bv = ov; bidx = oi; }
    }
    if (lane == 0){ swv[wid] = bv; swi[wid] = bidx; }
    __syncthreads();
    if (tid == 0){
      float mv = swv[0]; int mi = swi[0];
      #pragma unroll
      for (int w = 1; w < 8; w++)
        if (swv[w] > mv || (swv[w] == mv && swi[w] < mi)){ mv = swv[w]; mi = swi[w]; }
      sbi = mi; idxout[it] = mi;
    }
    __syncthreads();
    int w = sbi;
    if ((w & 255) == tid) v[w >> 8] = NEG_INF;
  }
}

// ----------------- edge conv -----------------
__global__ void edge_pq_kernel(const float* __restrict__ fext, int fSel, long fbstride,
                               int C, const float* __restrict__ W){
  const float* f = (fSel >= 0) ? bsel(fSel) : fext;
  int b = blockIdx.y;
  int n0 = blockIdx.x*32;
  const float* fb = f + (long)b*fbstride;
  __shared__ float sf[64][32];
  int nl = threadIdx.x & 31, og = threadIdx.x >> 5;
  for (int c = og; c < C; c += 8) sf[c][nl] = fb[(long)c*NP + n0 + nl];
  __syncthreads();
  #pragma unroll
  for (int j = 0; j < 8; j++){
    int o = og*8 + j;
    const float* w = W + (long)o*2*C;
    float ap = 0.f, aq = 0.f;
    for (int c = 0; c < C; c++){
      float fv = sf[c][nl];
      ap += w[c]*fv;
      aq += (w[C+c]-w[c])*fv;
    }
    long off = ((long)(b*NP + n0 + nl))*64 + o;
    g_pt[off] = ap; g_qt[off] = aq;
  }
}

__global__ void edge_gather_kernel(int chbase){
  int row = blockIdx.x; int b = row / NP, n = row % NP;
  int o = threadIdx.x;
  __shared__ int sidx[KNN];
  if (o < KNN) sidx[o] = g_idx[(long)row*KNN + o];
  __syncthreads();
  float q = g_qt[(long)row*64 + o];
  float mx = NEG_INF, s1 = 0.f, s2 = 0.f;
  const float* pb = g_pt + (long)b*NP*64;
  #pragma unroll 4
  for (int k = 0; k < KNN; k++){
    float v = pb[(long)sidx[k]*64 + o] + q;
    mx = fmaxf(mx, v); s1 += v; s2 += v*v;
  }
  g_xs[((long)b*128 + chbase + o)*NP + n] = mx;
  int slot = row & (NSLOT-1);
  atomicAdd(&g_ssum[o*NSLOT + slot], s1);
  atomicAdd(&g_ssq[o*NSLOT + slot], s2);
}

__global__ void sqnorm_kernel(){
  int i = blockIdx.x*blockDim.x + threadIdx.x;  // b*NP+n
  if (i >= NB*NP) return;
  int b = i / NP, n = i % NP;
  const float* f = g_xs + (long)b*128*NP + n;
  float s = 0.f;
  #pragma unroll 8
  for (int c = 0; c < 64; c++){ float v = f[(long)c*NP]; s += v*v; }
  g_xx[i] = s;
}

// ----------------- SA layer helpers -----------------
__global__ void qk_kernel(const float* __restrict__ Wq, const float* __restrict__ Wk){
  int b = blockIdx.y, n0 = blockIdx.x*32;
  __shared__ float sf[128][32];
  int nl = threadIdx.x & 31, og = threadIdx.x >> 5;
  const float* xb = g_xs + (long)b*128*NP;
  for (int c = og; c < 128; c += 8) sf[c][nl] = xb[(long)c*NP + n0 + nl];
  __syncthreads();
  #pragma unroll
  for (int j = 0; j < 4; j++){
    int qi = og*4 + j;
    const float* wq = Wq + qi*128;
    const float* wk = Wk + qi*128;
    float aq = 0.f, ak = 0.f;
    for (int c = 0; c < 128; c++){
      float fv = sf[c][nl];
      aq += wq[c]*fv; ak += wk[c]*fv;
    }
    g_q [((long)b*32 + qi)*NP + n0 + nl] = aq;
    g_kk[((long)b*32 + qi)*NP + n0 + nl] = ak;
  }
}

__global__ void softmax_kernel(){
  long row = blockIdx.x;
  float* p = g_big + row*(long)NP;
  int tid = threadIdx.x;
  int lane = tid & 31, wid = tid >> 5;
  __shared__ float sred[8];
  __shared__ float sres;
  float v[8];
  #pragma unroll
  for (int i = 0; i < 8; i++) v[i] = p[tid + i*256];
  float m = v[0];
  #pragma unroll
  for (int i = 1; i < 8; i++) m = fmaxf(m, v[i]);
  #pragma unroll
  for (int off = 16; off; off >>= 1) m = fmaxf(m, __shfl_xor_sync(0xffffffffu, m, off));
  if (lane == 0) sred[wid] = m;
  __syncthreads();
  if (tid == 0){
    float t = sred[0];
    #pragma unroll
    for (int w = 1; w < 8; w++) t = fmaxf(t, sred[w]);
    sres = t;
  }
  __syncthreads();
  float bmax = sres;
  float s = 0.f;
  #pragma unroll
  for (int i = 0; i < 8; i++){ v[i] = __expf(v[i] - bmax); s += v[i]; }
  #pragma unroll
  for (int off = 16; off; off >>= 1) s += __shfl_xor_sync(0xffffffffu, s, off);
  __syncthreads();
  if (lane == 0) sred[wid] = s;
  __syncthreads();
  if (tid == 0){
    float t = 0.f;
    #pragma unroll
    for (int w = 0; w < 8; w++) t += sred[w];
    sres = t;
  }
  __syncthreads();
  float inv = 1.f / sres;
  #pragma unroll
  for (int i = 0; i < 8; i++) p[tid + i*256] = v[i]*inv;
}

__global__ void colsum_kernel(){
  int b = blockIdx.y;
  int m = blockIdx.x*256 + threadIdx.x;
  const float* a = g_big + (long)b*NP*NP + m;
  float s0 = 0.f, s1 = 0.f, s2 = 0.f, s3 = 0.f;
  for (int n = 0; n < NP; n += 4){
    s0 += a[(long)n*NP];
    s1 += a[(long)(n+1)*NP];
    s2 += a[(long)(n+2)*NP];
    s3 += a[(long)(n+3)*NP];
  }
  g_cs[b*NP + m] = 1.f / (1e-6f + (s0+s1)+(s2+s3));
}

__global__ void residual_kernel(int layer){
  long i = (long)blockIdx.x*blockDim.x + threadIdx.x;
  long tot = (long)NB*128*NP;
  if (i >= tot) return;
  int n = (int)(i % NP); long t = i / NP;
  int c = (int)(t % 128); int b = (int)(t / 128);
  float tv = g_d[((long)b*128 + c)*NP + n];
  float r = (tv - g_mean[c]) * g_istd[c];
  r = r > 0.f ? r : 0.f;
  long xi = ((long)b*128 + c)*NP + n;
  float v = g_xs[xi] + r;
  g_xs[xi] = v;
  g_cat[((long)b*512 + layer*128 + c)*NP + n] = v;
}

// ----------------- fuse / head helpers -----------------
__global__ void gmax_kernel(){
  int row = blockIdx.x;                 // b*1024 + o
  int o = row & 1023;
  const float* p = g_tf + (long)row*NP;
  float m = NEG_INF;
  for (int n = threadIdx.x; n < NP; n += 128) m = fmaxf(m, p[n]);
  #pragma unroll
  for (int off = 16; off; off >>= 1) m = fmaxf(m, __shfl_xor_sync(0xffffffffu, m, off));
  __shared__ float sw[4];
  int lane = threadIdx.x & 31, wid = threadIdx.x >> 5;
  if (lane == 0) sw[wid] = m;
  __syncthreads();
  if (threadIdx.x == 0){
    float mm = fmaxf(fmaxf(sw[0], sw[1]), fmaxf(sw[2], sw[3]));
    float v = (mm - g_mean[o]) * g_istd[o];
    g_gm[row] = v > 0.f ? v : 0.f;
  }
}

__global__ void w1g_kernel(const float* __restrict__ Wc1){
  int o = blockIdx.x*8 + (threadIdx.x >> 5);
  int lane = threadIdx.x & 31;
  const float* w = Wc1 + (long)o*1536;
  float acc[NB];
  #pragma unroll
  for (int b = 0; b < NB; b++) acc[b] = 0.f;
  for (int c = lane; c < 1024; c += 32){
    float wv = w[c];
    #pragma unroll
    for (int b = 0; b < NB; b++) acc[b] += wv * g_gm[b*1024 + c];
  }
  #pragma unroll
  for (int b = 0; b < NB; b++){
    #pragma unroll
    for (int off = 16; off; off >>= 1) acc[b] += __shfl_xor_sync(0xffffffffu, acc[b], off);
  }
  if (lane == 0){
    #pragma unroll
    for (int b = 0; b < NB; b++) g_w1g[b*512 + o] = acc[b];
  }
}

// ----------------- tiled SGEMM: 64x128 tile, 4x8 micro, KT=32 -----------------
// C[b] = op(A[b]) * B[b]; op=A^T if TRANSA (A stored [K][M] row-major).
// EPI: 0 none, 1 pdist(2a - xx[row] - xx[col]), 3 stats,
//      4 stats+row-bias(E1[row]), 5 row-bias only,
//      6 xr-fused: v = E1[row*NP+col] - a*E2[col], + stats.
template<int EPI, bool TRANSA>
__global__ void __launch_bounds__(256)
gemm_kernel(int M, int K,
  const float* __restrict__ Aext, int aSel, int lda, long sA,
  int bSel, int ldb, long sB,
  float* __restrict__ Cext, int cSel, int ldc, long sC,
  const float* __restrict__ e1ext, int e1Sel, long se1,
  int e2Sel, long se2)
{
  int bb = blockIdx.z;
  const float* A = ((aSel >= 0) ? bsel(aSel) : Aext) + (long)bb*sA;
  const float* B = bsel(bSel) + (long)bb*sB;
  float* C = ((cSel >= 0) ? bsel(cSel) : Cext) + (long)bb*sC;
  const float* E1 = nullptr;
  if (EPI == 1 || EPI == 4 || EPI == 5 || EPI == 6)
    E1 = ((e1Sel >= 0) ? bsel(e1Sel) : e1ext) + (long)bb*se1;
  const float* E2 = nullptr;
  if (EPI == 6) E2 = bsel(e2Sel) + (long)bb*se2;

  int tm = blockIdx.y*64, tn = blockIdx.x*128;
  __shared__ float As[32][68];
  __shared__ float Bs[32][128];
  int tid = threadIdx.x;
  int tx = tid & 15, ty = tid >> 4;
  float acc[4][8] = {};

  for (int k0 = 0; k0 < K; k0 += 32){
    if (TRANSA){
      int kk = tid >> 4, mm = (tid & 15)*4;
      *(float4*)&As[kk   ][mm] = *(const float4*)&A[(long)(k0+kk   )*lda + tm + mm];
      *(float4*)&As[kk+16][mm] = *(const float4*)&A[(long)(k0+kk+16)*lda + tm + mm];
    } else {
      int rl = tid >> 2, kk = (tid & 3)*8;
      int row = tm + rl;
      float4 a0 = make_float4(0.f,0.f,0.f,0.f), a1 = a0;
      if (row < M){
        a0 = *(const float4*)&A[(long)row*lda + k0 + kk];
        a1 = *(const float4*)&A[(long)row*lda + k0 + kk + 4];
      }
      As[kk  ][rl] = a0.x; As[kk+1][rl] = a0.y; As[kk+2][rl] = a0.z; As[kk+3][rl] = a0.w;
      As[kk+4][rl] = a1.x; As[kk+5][rl] = a1.y; As[kk+6][rl] = a1.z; As[kk+7][rl] = a1.w;
    }
    {
      int kb = tid >> 4, nn = (tid & 15)*4;
      *(float4*)&Bs[kb   ][nn   ] = *(const float4*)&B[(long)(k0+kb   )*ldb + tn + nn];
      *(float4*)&Bs[kb   ][nn+64] = *(const float4*)&B[(long)(k0+kb   )*ldb + tn + nn + 64];
      *(float4*)&Bs[kb+16][nn   ] = *(const float4*)&B[(long)(k0+kb+16)*ldb + tn + nn];
      *(float4*)&Bs[kb+16][nn+64] = *(const float4*)&B[(long)(k0+kb+16)*ldb + tn + nn + 64];
    }
    __syncthreads();
    #pragma unroll
    for (int kk = 0; kk < 32; kk++){
      float4 a4 = *(float4*)&As[kk][ty*4];
      float4 b0 = *(float4*)&Bs[kk][tx*4];
      float4 b1 = *(float4*)&Bs[kk][64 + tx*4];
      float ar[4] = {a4.x, a4.y, a4.z, a4.w};
      float br[8] = {b0.x, b0.y, b0.z, b0.w, b1.x, b1.y, b1.z, b1.w};
      #pragma unroll
      for (int i = 0; i < 4; i++)
        #pragma unroll
        for (int j = 0; j < 8; j++)
          acc[i][j] += ar[i]*br[j];
    }
    __syncthreads();
  }

  int slot = (blockIdx.x + blockIdx.z) & (NSLOT-1);
  int c0 = tn + tx*4, c1 = tn + 64 + tx*4;
  #pragma unroll
  for (int i = 0; i < 4; i++){
    int row = tm + ty*4 + i;
    bool ok = row < M;
    float bias = 0.f;
    if ((EPI == 4 || EPI == 5) && ok) bias = E1[row];
    float out[8];
    float s1 = 0.f, s2 = 0.f;
    #pragma unroll
    for (int j = 0; j < 8; j++){
      int col = (j < 4) ? (c0 + j) : (c1 + j - 4);
      float v = acc[i][j];
      if (EPI == 1)      v = 2.f*v - (ok ? E1[row] : 0.f) - E1[col];
      else if (EPI == 6) v = (ok ? E1[(long)row*NP + col] : 0.f) - v*E2[col];
      else               v += bias;
      out[j] = v;
      if (EPI == 3 || EPI == 4 || EPI == 6){ s1 += v; s2 += v*v; }
    }
    if (ok){
      *(float4*)&C[(long)row*ldc + c0] = make_float4(out[0],out[1],out[2],out[3]);
      *(float4*)&C[(long)row*ldc + c1] = make_float4(out[4],out[5],out[6],out[7]);
    }
    if (EPI == 3 || EPI == 4 || EPI == 6){
      #pragma unroll
      for (int off = 8; off; off >>= 1){
        s1 += __shfl_xor_sync(0xffffffffu, s1, off);
        s2 += __shfl_xor_sync(0xffffffffu, s2, off);
      }
      if (tx == 0 && ok){
        atomicAdd(&g_ssum[row*NSLOT + slot], s1);
        atomicAdd(&g_ssq [row*NSLOT + slot], s2);
      }
    }
  }
}

// ----------------- host orchestration -----------------
extern "C" void kernel_launch(void* const* d_in, const int* in_sizes, int n_in,
                              void* d_out, int out_size) {
  (void)in_sizes; (void)n_in; (void)out_size;
  const float* x   = (const float*)d_in[0];
  const float* We1 = (const float*)d_in[1];
  const float* We2 = (const float*)d_in[3];
  const float* Wq  = (const float*)d_in[5];
  const float* Wk  = (const float*)d_in[6];
  const float* Wt  = (const float*)d_in[7];
  const float* Wf  = (const float*)d_in[9];
  const float* Wc1 = (const float*)d_in[11];
  const float* Wc2 = (const float*)d_in[13];
  const float* Wc3 = (const float*)d_in[15];
  const float* bc3 = (const float*)d_in[16];
  float* out = (float*)d_out;

  const long SBIG = (long)NP*NP;

  // ---- knn on xyz + edgeconv1 ----
  pdist1_kernel<<<NB*NP, 256>>>(x);
  topk_kernel<<<NB*NP, 256>>>();
  zero_slots_kernel<<<128, 256>>>();
  edge_pq_kernel<<<dim3(NP/32, NB), 256>>>(x, -1, (long)3*NP, 3, We1);
  edge_gather_kernel<<<NB*NP, 64>>>(0);
  bn_finalize_kernel<<<1, 64>>>(64, (float)((long)NB*NP*KNN));
  bn_relu_kernel<<<(NB*64*NP)/256, 256>>>(1, (long)128*NP, 64, 0);

  // ---- knn on f1 + edgeconv2 ----
  sqnorm_kernel<<<(NB*NP)/256, 256>>>();
  gemm_kernel<1, true><<<dim3(16, 32, NB), 256>>>(NP, 64,
      nullptr, 1, NP, (long)128*NP,
      1, NP, (long)128*NP,
      nullptr, 0, NP, SBIG,
      nullptr, 12, NP, -1, 0);
  topk_kernel<<<NB*NP, 256>>>();
  zero_slots_kernel<<<128, 256>>>();
  edge_pq_kernel<<<dim3(NP/32, NB), 256>>>(nullptr, 1, (long)128*NP, 64, We2);
  edge_gather_kernel<<<NB*NP, 64>>>(64);
  bn_finalize_kernel<<<1, 64>>>(64, (float)((long)NB*NP*KNN));
  bn_relu_kernel<<<(NB*64*NP)/256, 256>>>(1, (long)128*NP, 64, 64);

  // ---- 4 SA layers ----
  for (int i = 0; i < 4; i++){
    qk_kernel<<<dim3(NP/32, NB), 256>>>(Wq + (long)i*32*128, Wk + (long)i*32*128);
    gemm_kernel<0, true><<<dim3(16, 32, NB), 256>>>(NP, 32,
        nullptr, 4, NP, (long)32*NP,
        5, NP, (long)32*NP,
        nullptr, 0, NP, SBIG,
        nullptr, -1, 0, -1, 0);
    softmax_kernel<<<NB*NP, 256>>>();
    colsum_kernel<<<dim3(NP/256, NB), 256>>>();
    // y = Wt @ xs
    gemm_kernel<0, false><<<dim3(16, 2, NB), 256>>>(128, 128,
        Wt + (long)i*128*128, -1, 128, 0,
        1, NP, (long)128*NP,
        nullptr, 7, NP, (long)128*NP,
        nullptr, -1, 0, -1, 0);
    zero_slots_kernel<<<128, 256>>>();
    // t = y - (y @ attn) * cs  (+ BN stats)
    gemm_kernel<6, false><<<dim3(16, 2, NB), 256>>>(128, NP,
        nullptr, 7, NP, (long)128*NP,
        0, NP, SBIG,
        nullptr, 6, NP, (long)128*NP,
        nullptr, 7, (long)128*NP,
        8, NP);
    bn_finalize_kernel<<<1, 128>>>(128, (float)(NB*NP));
    residual_kernel<<<(NB*128*NP)/256, 256>>>(i);
  }

  // ---- fuse + global max ----
  zero_slots_kernel<<<128, 256>>>();
  gemm_kernel<3, false><<<dim3(16, 16, NB), 256>>>(1024, 512,
      Wf, -1, 512, 0,
      2, NP, (long)512*NP,
      nullptr, 9, NP, (long)1024*NP,
      nullptr, -1, 0, -1, 0);
  bn_finalize_kernel<<<8, 128>>>(1024, (float)(NB*NP));
  gmax_kernel<<<NB*1024, 128>>>();
  w1g_kernel<<<64, 256>>>(Wc1);

  // ---- head ----
  zero_slots_kernel<<<128, 256>>>();
  gemm_kernel<4, false><<<dim3(16, 8, NB), 256>>>(512, 512,
      Wc1 + 1024, -1, 1536, 0,
      2, NP, (long)512*NP,
      nullptr, 10, NP, (long)512*NP,
      nullptr, 13, 512,
      -1, 0);
  bn_finalize_kernel<<<4, 128>>>(512, (float)(NB*NP));
  bn_relu_kernel<<<(NB*512*NP)/256, 256>>>(10, (long)512*NP, 512, 0);

  zero_slots_kernel<<<128, 256>>>();
  gemm_kernel<3, false><<<dim3(16, 4, NB), 256>>>(256, 512,
      Wc2, -1, 512, 0,
      10, NP, (long)512*NP,
      nullptr, 11, NP, (long)256*NP,
      nullptr, -1, 0, -1, 0);
  bn_finalize_kernel<<<2, 128>>>(256, (float)(NB*NP));
  bn_relu_kernel<<<(NB*256*NP)/256, 256>>>(11, (long)256*NP, 256, 0);

  gemm_kernel<5, false><<<dim3(16, 1, NB), 256>>>(13, 256,
      Wc3, -1, 256, 0,
      11, NP, (long)256*NP,
      out, -1, NP, (long)13*NP,
      bc3, -1, 0,
      -1, 0);
}

// round 8
// speedup vs baseline: 1.2349x; 1.1085x over previous
#include <cuda_runtime.h>
#include <cuda_bf16.h>
#include <cstdint>

#define NB 8
#define NP 2048
#define KNN 32
#define NSLOT 32
#define EPSBN 1e-5f
#define NEG_INF -3.402823466e38f

typedef __nv_bfloat16 bf16;

// ----------------- static device scratch (no runtime allocation) -----------------
__device__ float g_big[(size_t)NB*NP*NP];     // pdist / energy (fp32)
__device__ bf16  g_ah[(size_t)NB*NP*NP];      // attn hi plane
__device__ bf16  g_al[(size_t)NB*NP*NP];      // attn lo plane
__device__ int   g_idx[(size_t)NB*NP*KNN];
__device__ float g_xx[NB*NP];
__device__ float g_xs[(size_t)NB*128*NP];     // running SA features (fp32)
__device__ bf16  g_xsh[(size_t)NB*128*NP];
__device__ bf16  g_xsl[(size_t)NB*128*NP];
__device__ bf16  g_ch[(size_t)NB*512*NP];     // cat planes
__device__ bf16  g_cl[(size_t)NB*512*NP];
__device__ float g_pt[(size_t)NB*NP*64];
__device__ float g_qt[(size_t)NB*NP*64];
__device__ bf16  g_qh[(size_t)NB*NP*32];      // q^T planes (point-major, lda=32)
__device__ bf16  g_ql[(size_t)NB*NP*32];
__device__ bf16  g_kh[(size_t)NB*32*NP];      // k planes [32][NP]
__device__ bf16  g_kl[(size_t)NB*32*NP];
__device__ float g_d[(size_t)NB*128*NP];      // t pre-BN
__device__ float g_t[(size_t)NB*128*NP];      // y = Wt @ xs (fp32)
__device__ bf16  g_yh[(size_t)NB*128*NP];
__device__ bf16  g_yl[(size_t)NB*128*NP];
__device__ float g_cs[NB*NP];
__device__ float g_tf[(size_t)NB*1024*NP];    // fuse pre-BN
__device__ float g_h1[(size_t)NB*512*NP];
__device__ bf16  g_h1h[(size_t)NB*512*NP];    // relu(bn(h1)) planes
__device__ bf16  g_h1l[(size_t)NB*512*NP];
__device__ float g_h2[(size_t)NB*256*NP];
__device__ float g_gm[NB*1024];
__device__ float g_w1g[NB*512];
__device__ bf16  g_wfh[1024*512]; __device__ bf16 g_wfl[1024*512];
__device__ bf16  g_w1h[512*512];  __device__ bf16 g_w1l[512*512];
__device__ bf16  g_w2h[256*512];  __device__ bf16 g_w2l[256*512];
__device__ bf16  g_wth[128*128];  __device__ bf16 g_wtl[128*128];
__device__ float g_ssum[1024*NSLOT];
__device__ float g_ssq[1024*NSLOT];
__device__ float g_mean[1024];
__device__ float g_istd[1024];

__device__ __forceinline__ float* bsel(int s){
  switch(s){
    case 0: return g_big;  case 1: return g_xs;
    case 11: return g_h2;  case 12: return g_xx;
  }
  return nullptr;
}

// ----------------- small utility kernels -----------------
__global__ void zero_slots_kernel(){
  int i = blockIdx.x*256 + threadIdx.x;
  if (i < 1024*NSLOT){ g_ssum[i] = 0.f; g_ssq[i] = 0.f; }
}

__global__ void bn_finalize_kernel(int C, float count){
  int c = blockIdx.x*blockDim.x + threadIdx.x;
  if (c >= C) return;
  float s1 = 0.f, s2 = 0.f;
  for (int s = 0; s < NSLOT; s++){ s1 += g_ssum[c*NSLOT+s]; s2 += g_ssq[c*NSLOT+s]; }
  float m = s1 / count;
  float var = s2 / count - m*m;
  g_mean[c] = m;
  g_istd[c] = rsqrtf(fmaxf(var, 0.f) + EPSBN);
}

__global__ void bn_relu_kernel(int dSel, long bstride, int C, int choff){
  float* data = bsel(dSel);
  long i = (long)blockIdx.x*blockDim.x + threadIdx.x;
  long tot = (long)NB*C*NP;
  if (i >= tot) return;
  int n = (int)(i % NP); long t = i / NP;
  int c = (int)(t % C);  int b = (int)(t / C);
  float* p = data + (long)b*bstride + (long)(choff+c)*NP + n;
  float v = (*p - g_mean[c]) * g_istd[c];
  *p = v > 0.f ? v : 0.f;
}

// relu(bn(src)) -> bf16 planes only (h1 path); layout [b][C][NP] packed
__global__ void bn_relu_planes_kernel(const float* __restrict__ src, int C,
                                      bf16* __restrict__ H, bf16* __restrict__ L){
  long i = (long)blockIdx.x*blockDim.x + threadIdx.x;
  long tot = (long)NB*C*NP;
  if (i >= tot) return;
  int c = (int)((i / NP) % C);
  float v = (src[i] - g_mean[c]) * g_istd[c];
  v = v > 0.f ? v : 0.f;
  bf16 hi = __float2bfloat16(v);
  H[i] = hi; L[i] = __float2bfloat16(v - __bfloat162float(hi));
}

// generic fp32 -> split planes (packed [total] with source ld)
__global__ void to_planes_kernel(const float* __restrict__ src, long total, int cols, int ld,
                                 bf16* __restrict__ H, bf16* __restrict__ L){
  long i = (long)blockIdx.x*256 + threadIdx.x;
  if (i >= total) return;
  long r = i / cols; int c = (int)(i % cols);
  float v = src[r*(long)ld + c];
  bf16 hi = __float2bfloat16(v);
  H[i] = hi; L[i] = __float2bfloat16(v - __bfloat162float(hi));
}

// ----------------- knn -----------------
__global__ void pdist1_kernel(const float* __restrict__ x){
  int row = blockIdx.x;
  int b = row / NP, n = row % NP;
  const float* xb = x + (long)b*3*NP;
  float cx = xb[n], cy = xb[NP+n], cz = xb[2*NP+n];
  float* out = g_big + (long)row*NP;
  for (int m = threadIdx.x; m < NP; m += blockDim.x){
    float dx = xb[m]-cx, dy = xb[NP+m]-cy, dz = xb[2*NP+m]-cz;
    out[m] = -(dx*dx + dy*dy + dz*dz);
  }
}

__global__ void topk_kernel(){
  int row = blockIdx.x;
  const float* src = g_big + (long)row*NP;
  int tid = threadIdx.x;
  float v[8];
  #pragma unroll
  for (int i = 0; i < 8; i++) v[i] = src[tid + i*256];
  __shared__ float swv[8]; __shared__ int swi[8]; __shared__ int sbi;
  int lane = tid & 31, wid = tid >> 5;
  int* idxout = g_idx + (long)row*KNN;
  for (int it = 0; it < KNN; it++){
    float bv = v[0]; int bs = 0;
    #pragma unroll
    for (int i = 1; i < 8; i++) if (v[i] > bv){ bv = v[i]; bs = i; }
    int bidx = tid + bs*256;
    #pragma unroll
    for (int off = 16; off; off >>= 1){
      float ov = __shfl_down_sync(0xffffffffu, bv, off);
      int   oi = __shfl_down_sync(0xffffffffu, bidx, off);
      if (ov > bv || (ov == bv && oi < bidx)){ bv = ov; bidx = oi; }
    }
    if (lane == 0){ swv[wid] = bv; swi[wid] = bidx; }
    __syncthreads();
    if (tid == 0){
      float mv = swv[0]; int mi = swi[0];
      #pragma unroll
      for (int w = 1; w < 8; w++)
        if (swv[w] > mv || (swv[w] == mv && swi[w] < mi)){ mv = swv[w]; mi = swi[w]; }
      sbi = mi; idxout[it] = mi;
    }
    __syncthreads();
    int w = sbi;
    if ((w & 255) == tid) v[w >> 8] = NEG_INF;
  }
}

// ----------------- edge conv -----------------
__global__ void edge_pq_kernel(const float* __restrict__ fext, int fSel, long fbstride,
                               int C, const float* __restrict__ W){
  const float* f = (fSel >= 0) ? bsel(fSel) : fext;
  int b = blockIdx.y;
  int n0 = blockIdx.x*32;
  const float* fb = f + (long)b*fbstride;
  __shared__ float sf[64][32];
  int nl = threadIdx.x & 31, og = threadIdx.x >> 5;
  for (int c = og; c < C; c += 8) sf[c][nl] = fb[(long)c*NP + n0 + nl];
  __syncthreads();
  #pragma unroll
  for (int j = 0; j < 8; j++){
    int o = og*8 + j;
    const float* w = W + (long)o*2*C;
    float ap = 0.f, aq = 0.f;
    for (int c = 0; c < C; c++){
      float fv = sf[c][nl];
      ap += w[c]*fv;
      aq += (w[C+c]-w[c])*fv;
    }
    long off = ((long)(b*NP + n0 + nl))*64 + o;
    g_pt[off] = ap; g_qt[off] = aq;
  }
}

__global__ void edge_gather_kernel(int chbase){
  int row = blockIdx.x; int b = row / NP, n = row % NP;
  int o = threadIdx.x;
  __shared__ int sidx[KNN];
  if (o < KNN) sidx[o] = g_idx[(long)row*KNN + o];
  __syncthreads();
  float q = g_qt[(long)row*64 + o];
  float mx = NEG_INF, s1 = 0.f, s2 = 0.f;
  const float* pb = g_pt + (long)b*NP*64;
  #pragma unroll 4
  for (int k = 0; k < KNN; k++){
    float v = pb[(long)sidx[k]*64 + o] + q;
    mx = fmaxf(mx, v); s1 += v; s2 += v*v;
  }
  g_xs[((long)b*128 + chbase + o)*NP + n] = mx;
  int slot = row & (NSLOT-1);
  atomicAdd(&g_ssum[o*NSLOT + slot], s1);
  atomicAdd(&g_ssq[o*NSLOT + slot], s2);
}

__global__ void sqnorm_kernel(){
  int i = blockIdx.x*blockDim.x + threadIdx.x;
  if (i >= NB*NP) return;
  int b = i / NP, n = i % NP;
  const float* f = g_xs + (long)b*128*NP + n;
  float s = 0.f;
  #pragma unroll 8
  for (int c = 0; c < 64; c++){ float v = f[(long)c*NP]; s += v*v; }
  g_xx[i] = s;
}

// ----------------- SA layer helpers -----------------
__global__ void qk_kernel(const float* __restrict__ Wq, const float* __restrict__ Wk,
                          bf16* __restrict__ qTh, bf16* __restrict__ qTl,
                          bf16* __restrict__ kh, bf16* __restrict__ kl){
  int b = blockIdx.y, n0 = blockIdx.x*32;
  __shared__ float sf[128][32];
  int nl = threadIdx.x & 31, og = threadIdx.x >> 5;
  const float* xb = g_xs + (long)b*128*NP;
  for (int c = og; c < 128; c += 8) sf[c][nl] = xb[(long)c*NP + n0 + nl];
  __syncthreads();
  #pragma unroll
  for (int j = 0; j < 4; j++){
    int qi = og*4 + j;
    const float* wq = Wq + qi*128;
    const float* wk = Wk + qi*128;
    float aq = 0.f, ak = 0.f;
    for (int c = 0; c < 128; c++){
      float fv = sf[c][nl];
      aq += wq[c]*fv; ak += wk[c]*fv;
    }
    bf16 qh = __float2bfloat16(aq);
    bf16 ql = __float2bfloat16(aq - __bfloat162float(qh));
    bf16 kh2 = __float2bfloat16(ak);
    bf16 kl2 = __float2bfloat16(ak - __bfloat162float(kh2));
    long qoff = ((long)b*NP + n0 + nl)*32 + qi;
    qTh[qoff] = qh; qTl[qoff] = ql;
    long koff = ((long)b*32 + qi)*NP + n0 + nl;
    kh[koff] = kh2; kl[koff] = kl2;
  }
}

// softmax over rows of g_big -> write bf16 hi/lo planes
__global__ void softmax_kernel(bf16* __restrict__ ah, bf16* __restrict__ al){
  long row = blockIdx.x;
  const float* p = g_big + row*(long)NP;
  int tid = threadIdx.x;
  int lane = tid & 31, wid = tid >> 5;
  __shared__ float sred[8];
  __shared__ float sres;
  float v[8];
  #pragma unroll
  for (int i = 0; i < 8; i++) v[i] = p[tid + i*256];
  float m = v[0];
  #pragma unroll
  for (int i = 1; i < 8; i++) m = fmaxf(m, v[i]);
  #pragma unroll
  for (int off = 16; off; off >>= 1) m = fmaxf(m, __shfl_xor_sync(0xffffffffu, m, off));
  if (lane == 0) sred[wid] = m;
  __syncthreads();
  if (tid == 0){
    float t = sred[0];
    #pragma unroll
    for (int w = 1; w < 8; w++) t = fmaxf(t, sred[w]);
    sres = t;
  }
  __syncthreads();
  float bmax = sres;
  float s = 0.f;
  #pragma unroll
  for (int i = 0; i < 8; i++){ v[i] = __expf(v[i] - bmax); s += v[i]; }
  #pragma unroll
  for (int off = 16; off; off >>= 1) s += __shfl_xor_sync(0xffffffffu, s, off);
  __syncthreads();
  if (lane == 0) sred[wid] = s;
  __syncthreads();
  if (tid == 0){
    float t = 0.f;
    #pragma unroll
    for (int w = 0; w < 8; w++) t += sred[w];
    sres = t;
  }
  __syncthreads();
  float inv = 1.f / sres;
  #pragma unroll
  for (int i = 0; i < 8; i++){
    float w = v[i]*inv;
    bf16 hi = __float2bfloat16(w);
    long off = row*(long)NP + tid + i*256;
    ah[off] = hi; al[off] = __float2bfloat16(w - __bfloat162float(hi));
  }
}

__global__ void colsum_kernel(const bf16* __restrict__ ah, const bf16* __restrict__ al){
  int b = blockIdx.y;
  int m = blockIdx.x*256 + threadIdx.x;
  const bf16* A = ah + (long)b*NP*NP + m;
  const bf16* L = al + (long)b*NP*NP + m;
  float s = 0.f;
  for (int n = 0; n < NP; n++)
    s += __bfloat162float(A[(long)n*NP]) + __bfloat162float(L[(long)n*NP]);
  g_cs[b*NP + m] = 1.f / (1e-6f + s);
}

// residual: xs += relu(bn(t)); write xs planes + cat plane slice
__global__ void residual_kernel(int layer,
                                bf16* __restrict__ xsh, bf16* __restrict__ xsl,
                                bf16* __restrict__ ch, bf16* __restrict__ cl){
  long i = (long)blockIdx.x*blockDim.x + threadIdx.x;
  long tot = (long)NB*128*NP;
  if (i >= tot) return;
  int n = (int)(i % NP); long t = i / NP;
  int c = (int)(t % 128); int b = (int)(t / 128);
  long xi = ((long)b*128 + c)*NP + n;
  float tv = g_d[xi];
  float r = (tv - g_mean[c]) * g_istd[c];
  r = r > 0.f ? r : 0.f;
  float v = g_xs[xi] + r;
  g_xs[xi] = v;
  bf16 hi = __float2bfloat16(v);
  bf16 lo = __float2bfloat16(v - __bfloat162float(hi));
  xsh[xi] = hi; xsl[xi] = lo;
  long ci = ((long)b*512 + layer*128 + c)*NP + n;
  ch[ci] = hi; cl[ci] = lo;
}

// ----------------- fuse / head helpers -----------------
__global__ void gmax_kernel(){
  int row = blockIdx.x;
  int o = row & 1023;
  const float* p = g_tf + (long)row*NP;
  float m = NEG_INF;
  for (int n = threadIdx.x; n < NP; n += 128) m = fmaxf(m, p[n]);
  #pragma unroll
  for (int off = 16; off; off >>= 1) m = fmaxf(m, __shfl_xor_sync(0xffffffffu, m, off));
  __shared__ float sw[4];
  int lane = threadIdx.x & 31, wid = threadIdx.x >> 5;
  if (lane == 0) sw[wid] = m;
  __syncthreads();
  if (threadIdx.x == 0){
    float mm = fmaxf(fmaxf(sw[0], sw[1]), fmaxf(sw[2], sw[3]));
    float v = (mm - g_mean[o]) * g_istd[o];
    g_gm[row] = v > 0.f ? v : 0.f;
  }
}

__global__ void w1g_kernel(const float* __restrict__ Wc1){
  int o = blockIdx.x*8 + (threadIdx.x >> 5);
  int lane = threadIdx.x & 31;
  const float* w = Wc1 + (long)o*1536;
  float acc[NB];
  #pragma unroll
  for (int b = 0; b < NB; b++) acc[b] = 0.f;
  for (int c = lane; c < 1024; c += 32){
    float wv = w[c];
    #pragma unroll
    for (int b = 0; b < NB; b++) acc[b] += wv * g_gm[b*1024 + c];
  }
  #pragma unroll
  for (int b = 0; b < NB; b++){
    #pragma unroll
    for (int off = 16; off; off >>= 1) acc[b] += __shfl_xor_sync(0xffffffffu, acc[b], off);
  }
  if (lane == 0){
    #pragma unroll
    for (int b = 0; b < NB; b++) g_w1g[b*512 + o] = acc[b];
  }
}

// ----------------- tensor-core bf16-split GEMM -----------------
__device__ __forceinline__ uint32_t smem_u32(const void* p){
  return (uint32_t)__cvta_generic_to_shared(p);
}
__device__ __forceinline__ void ldm_x4(uint32_t a, uint32_t &r0, uint32_t &r1, uint32_t &r2, uint32_t &r3){
  asm volatile("ldmatrix.sync.aligned.m8n8.x4.shared.b16 {%0,%1,%2,%3}, [%4];"
    : "=r"(r0),"=r"(r1),"=r"(r2),"=r"(r3) : "r"(a));
}
__device__ __forceinline__ void ldm_x4t(uint32_t a, uint32_t &r0, uint32_t &r1, uint32_t &r2, uint32_t &r3){
  asm volatile("ldmatrix.sync.aligned.m8n8.x4.trans.shared.b16 {%0,%1,%2,%3}, [%4];"
    : "=r"(r0),"=r"(r1),"=r"(r2),"=r"(r3) : "r"(a));
}
__device__ __forceinline__ void mma16816(float* d, const uint32_t* a, const uint32_t* b){
  asm volatile("mma.sync.aligned.m16n8k16.row.col.f32.bf16.bf16.f32 "
    "{%0,%1,%2,%3}, {%4,%5,%6,%7}, {%8,%9}, {%0,%1,%2,%3};"
    : "+f"(d[0]),"+f"(d[1]),"+f"(d[2]),"+f"(d[3])
    : "r"(a[0]),"r"(a[1]),"r"(a[2]),"r"(a[3]), "r"(b[0]),"r"(b[1]));
}

// C[b](M x 2048) = A[b](M x K, planes, lda) * B[b](K x 2048, planes, ldb=NP)
// EPI: 0 plain, 3 stats, 4 stats+rowbias(E1[b][row]), 6 xr: v=E1[row*NP+col]-a*E2[col] +stats
// POUT: also emit bf16 hi/lo planes of C.
template<int EPI, bool POUT>
__global__ void __launch_bounds__(256)
mma_gemm(int M, int K,
  const bf16* __restrict__ Ah, const bf16* __restrict__ Al, int lda, long sA,
  const bf16* __restrict__ Bh, const bf16* __restrict__ Bl, long sB,
  float* __restrict__ Cc, int ldc, long sC,
  bf16* __restrict__ Ph, bf16* __restrict__ Pl,
  const float* __restrict__ E1, long se1,
  const float* __restrict__ E2, long se2)
{
  __shared__ bf16 As[2][128][40];
  __shared__ bf16 Bs[2][32][136];
  int bb = blockIdx.z;
  const bf16* Ap[2] = {Ah + (long)bb*sA, Al + (long)bb*sA};
  const bf16* Bp[2] = {Bh + (long)bb*sB, Bl + (long)bb*sB};
  float* C = Cc + (long)bb*sC;
  const float* e1 = nullptr; const float* e2 = nullptr;
  if (EPI == 4 || EPI == 6) e1 = E1 + (long)bb*se1;
  if (EPI == 6) e2 = E2 + (long)bb*se2;

  int tm = blockIdx.y*128, tn = blockIdx.x*128;
  int tid = threadIdx.x, lane = tid & 31, wid = tid >> 5;
  int wm = wid >> 2, wn = wid & 3;

  float acc[4][4][4];
  #pragma unroll
  for (int i = 0; i < 4; i++)
    #pragma unroll
    for (int j = 0; j < 4; j++)
      #pragma unroll
      for (int u = 0; u < 4; u++) acc[i][j][u] = 0.f;

  int fr = lane & 15, fs = lane >> 4;  // ldmatrix lane row / half-select

  for (int k0 = 0; k0 < K; k0 += 32){
    #pragma unroll
    for (int l = 0; l < 4; l++){
      int li = tid + l*256;
      int p = li >> 9, s = li & 511;
      int r = s >> 2, seg = (s & 3)*8;
      uint4 v = *(const uint4*)&Ap[p][(long)(tm + r)*lda + k0 + seg];
      *(uint4*)&As[p][r][seg] = v;
    }
    #pragma unroll
    for (int l = 0; l < 4; l++){
      int li = tid + l*256;
      int p = li >> 9, s = li & 511;
      int kk = s >> 4, seg = (s & 15)*8;
      uint4 v = *(const uint4*)&Bp[p][(long)(k0 + kk)*NP + tn + seg];
      *(uint4*)&Bs[p][kk][seg] = v;
    }
    __syncthreads();
    #pragma unroll
    for (int ks = 0; ks < 2; ks++){
      uint32_t aF[2][4][4], bF[2][4][2];
      #pragma unroll
      for (int p = 0; p < 2; p++){
        #pragma unroll
        for (int i = 0; i < 4; i++){
          uint32_t ad = smem_u32(&As[p][wm*64 + i*16 + fr][ks*16 + fs*8]);
          ldm_x4(ad, aF[p][i][0], aF[p][i][1], aF[p][i][2], aF[p][i][3]);
        }
        #pragma unroll
        for (int j2 = 0; j2 < 2; j2++){
          uint32_t ad = smem_u32(&Bs[p][ks*16 + fr][wn*32 + j2*16 + fs*8]);
          ldm_x4t(ad, bF[p][j2*2][0], bF[p][j2*2][1], bF[p][j2*2+1][0], bF[p][j2*2+1][1]);
        }
      }
      #pragma unroll
      for (int i = 0; i < 4; i++)
        #pragma unroll
        for (int j = 0; j < 4; j++){
          mma16816(acc[i][j], aF[0][i], bF[0][j]);
          mma16816(acc[i][j], aF[0][i], bF[1][j]);
          mma16816(acc[i][j], aF[1][i], bF[0][j]);
        }
    }
    __syncthreads();
  }

  int gr = lane >> 2, cp = (lane & 3)*2;
  int slot = (blockIdx.x + blockIdx.z*5) & (NSLOT-1);
  float s1[4][2], s2[4][2];
  #pragma unroll
  for (int i = 0; i < 4; i++){ s1[i][0]=s1[i][1]=0.f; s2[i][0]=s2[i][1]=0.f; }

  #pragma unroll
  for (int i = 0; i < 4; i++){
    #pragma unroll
    for (int h = 0; h < 2; h++){
      int row = tm + wm*64 + i*16 + gr + h*8;
      float rowbias = (EPI == 4) ? e1[row] : 0.f;
      #pragma unroll
      for (int j = 0; j < 4; j++){
        int col = tn + wn*32 + j*8 + cp;
        #pragma unroll
        for (int u = 0; u < 2; u++){
          float v = acc[i][j][h*2 + u];
          int cc = col + u;
          if (EPI == 6) v = e1[(long)row*NP + cc] - v*e2[cc];
          else v += rowbias;
          C[(long)row*ldc + cc] = v;
          if (POUT){
            bf16 hi = __float2bfloat16(v);
            long po = (long)bb*sC + (long)row*ldc + cc;
            Ph[po] = hi; Pl[po] = __float2bfloat16(v - __bfloat162float(hi));
          }
          if (EPI == 3 || EPI == 4 || EPI == 6){ s1[i][h] += v; s2[i][h] += v*v; }
        }
      }
    }
  }
  if (EPI == 3 || EPI == 4 || EPI == 6){
    #pragma unroll
    for (int i = 0; i < 4; i++)
      #pragma unroll
      for (int h = 0; h < 2; h++){
        float a1 = s1[i][h], a2 = s2[i][h];
        a1 += __shfl_xor_sync(0xffffffffu, a1, 1); a2 += __shfl_xor_sync(0xffffffffu, a2, 1);
        a1 += __shfl_xor_sync(0xffffffffu, a1, 2); a2 += __shfl_xor_sync(0xffffffffu, a2, 2);
        if ((lane & 3) == 0){
          int row = tm + wm*64 + i*16 + gr + h*8;
          atomicAdd(&g_ssum[row*NSLOT + slot], a1);
          atomicAdd(&g_ssq [row*NSLOT + slot], a2);
        }
      }
  }
}

// ----------------- fp32 tiled SGEMM (pdist2 gram + final Wc3 only) -----------------
template<int EPI, bool TRANSA>
__global__ void __launch_bounds__(256)
gemm_kernel(int M, int K,
  const float* __restrict__ Aext, int aSel, int lda, long sA,
  int bSel, int ldb, long sB,
  float* __restrict__ Cext, int cSel, int ldc, long sC,
  const float* __restrict__ e1ext, int e1Sel, long se1,
  int e2Sel, long se2)
{
  int bb = blockIdx.z;
  const float* A = ((aSel >= 0) ? bsel(aSel) : Aext) + (long)bb*sA;
  const float* B = bsel(bSel) + (long)bb*sB;
  float* C = ((cSel >= 0) ? bsel(cSel) : Cext) + (long)bb*sC;
  const float* E1 = nullptr;
  if (EPI == 1 || EPI == 5)
    E1 = ((e1Sel >= 0) ? bsel(e1Sel) : e1ext) + (long)bb*se1;

  int tm = blockIdx.y*64, tn = blockIdx.x*128;
  __shared__ float As[32][68];
  __shared__ float Bs[32][128];
  int tid = threadIdx.x;
  int tx = tid & 15, ty = tid >> 4;
  float acc[4][8] = {};

  for (int k0 = 0; k0 < K; k0 += 32){
    if (TRANSA){
      int kk = tid >> 4, mm = (tid & 15)*4;
      *(float4*)&As[kk   ][mm] = *(const float4*)&A[(long)(k0+kk   )*lda + tm + mm];
      *(float4*)&As[kk+16][mm] = *(const float4*)&A[(long)(k0+kk+16)*lda + tm + mm];
    } else {
      int rl = tid >> 2, kk = (tid & 3)*8;
      int row = tm + rl;
      float4 a0 = make_float4(0.f,0.f,0.f,0.f), a1 = a0;
      if (row < M){
        a0 = *(const float4*)&A[(long)row*lda + k0 + kk];
        a1 = *(const float4*)&A[(long)row*lda + k0 + kk + 4];
      }
      As[kk  ][rl] = a0.x; As[kk+1][rl] = a0.y; As[kk+2][rl] = a0.z; As[kk+3][rl] = a0.w;
      As[kk+4][rl] = a1.x; As[kk+5][rl] = a1.y; As[kk+6][rl] = a1.z; As[kk+7][rl] = a1.w;
    }
    {
      int kb = tid >> 4, nn = (tid & 15)*4;
      *(float4*)&Bs[kb   ][nn   ] = *(const float4*)&B[(long)(k0+kb   )*ldb + tn + nn];
      *(float4*)&Bs[kb   ][nn+64] = *(const float4*)&B[(long)(k0+kb   )*ldb + tn + nn + 64];
      *(float4*)&Bs[kb+16][nn   ] = *(const float4*)&B[(long)(k0+kb+16)*ldb + tn + nn];
      *(float4*)&Bs[kb+16][nn+64] = *(const float4*)&B[(long)(k0+kb+16)*ldb + tn + nn + 64];
    }
    __syncthreads();
    #pragma unroll
    for (int kk = 0; kk < 32; kk++){
      float4 a4 = *(float4*)&As[kk][ty*4];
      float4 b0 = *(float4*)&Bs[kk][tx*4];
      float4 b1 = *(float4*)&Bs[kk][64 + tx*4];
      float ar[4] = {a4.x, a4.y, a4.z, a4.w};
      float br[8] = {b0.x, b0.y, b0.z, b0.w, b1.x, b1.y, b1.z, b1.w};
      #pragma unroll
      for (int i = 0; i < 4; i++)
        #pragma unroll
        for (int j = 0; j < 8; j++)
          acc[i][j] += ar[i]*br[j];
    }
    __syncthreads();
  }

  int c0 = tn + tx*4, c1 = tn + 64 + tx*4;
  #pragma unroll
  for (int i = 0; i < 4; i++){
    int row = tm + ty*4 + i;
    bool ok = row < M;
    float bias = 0.f;
    if (EPI == 5 && ok) bias = E1[row];
    float out[8];
    #pragma unroll
    for (int j = 0; j < 8; j++){
      int col = (j < 4) ? (c0 + j) : (c1 + j - 4);
      float v = acc[i][j];
      if (EPI == 1) v = 2.f*v - (ok ? E1[row] : 0.f) - E1[col];
      else          v += bias;
      out[j] = v;
    }
    if (ok){
      *(float4*)&C[(long)row*ldc + c0] = make_float4(out[0],out[1],out[2],out[3]);
      *(float4*)&C[(long)row*ldc + c1] = make_float4(out[4],out[5],out[6],out[7]);
    }
  }
}

// ----------------- host orchestration -----------------
#define SYMADDR(var, sym) void* var##_v; cudaGetSymbolAddress(&var##_v, sym);
extern "C" void kernel_launch(void* const* d_in, const int* in_sizes, int n_in,
                              void* d_out, int out_size) {
  (void)in_sizes; (void)n_in; (void)out_size;
  const float* x   = (const float*)d_in[0];
  const float* We1 = (const float*)d_in[1];
  const float* We2 = (const float*)d_in[3];
  const float* Wq  = (const float*)d_in[5];
  const float* Wk  = (const float*)d_in[6];
  const float* Wt  = (const float*)d_in[7];
  const float* Wf  = (const float*)d_in[9];
  const float* Wc1 = (const float*)d_in[11];
  const float* Wc2 = (const float*)d_in[13];
  const float* Wc3 = (const float*)d_in[15];
  const float* bc3 = (const float*)d_in[16];
  float* out = (float*)d_out;

  // resolve device scratch addresses (no allocation; just symbol lookup)
  SYMADDR(ah, g_ah)   SYMADDR(al, g_al)
  SYMADDR(xsh, g_xsh) SYMADDR(xsl, g_xsl)
  SYMADDR(ch, g_ch)   SYMADDR(cl, g_cl)
  SYMADDR(qh, g_qh)   SYMADDR(ql, g_ql)
  SYMADDR(kh, g_kh)   SYMADDR(kl, g_kl)
  SYMADDR(yh, g_yh)   SYMADDR(yl, g_yl)
  SYMADDR(h1h, g_h1h) SYMADDR(h1l, g_h1l)
  SYMADDR(wfh, g_wfh) SYMADDR(wfl, g_wfl)
  SYMADDR(w1h, g_w1h) SYMADDR(w1l, g_w1l)
  SYMADDR(w2h, g_w2h) SYMADDR(w2l, g_w2l)
  SYMADDR(wth, g_wth) SYMADDR(wtl, g_wtl)
  SYMADDR(xs, g_xs)   SYMADDR(big, g_big)
  SYMADDR(tb, g_t)    SYMADDR(db, g_d)
  SYMADDR(cs, g_cs)   SYMADDR(tf, g_tf)
  SYMADDR(h1, g_h1)   SYMADDR(h2, g_h2)
  SYMADDR(w1gp, g_w1g)
  bf16 *p_ah=(bf16*)ah_v, *p_al=(bf16*)al_v, *p_xsh=(bf16*)xsh_v, *p_xsl=(bf16*)xsl_v;
  bf16 *p_ch=(bf16*)ch_v, *p_cl=(bf16*)cl_v, *p_qh=(bf16*)qh_v, *p_ql=(bf16*)ql_v;
  bf16 *p_kh=(bf16*)kh_v, *p_kl=(bf16*)kl_v;
  bf16 *p_yh=(bf16*)yh_v, *p_yl=(bf16*)yl_v, *p_h1h=(bf16*)h1h_v, *p_h1l=(bf16*)h1l_v;
  bf16 *p_wfh=(bf16*)wfh_v, *p_wfl=(bf16*)wfl_v, *p_w1h=(bf16*)w1h_v, *p_w1l=(bf16*)w1l_v;
  bf16 *p_w2h=(bf16*)w2h_v, *p_w2l=(bf16*)w2l_v, *p_wth=(bf16*)wth_v, *p_wtl=(bf16*)wtl_v;
  float *p_xs=(float*)xs_v, *p_big=(float*)big_v, *p_t=(float*)tb_v, *p_d=(float*)db_v;
  float *p_cs=(float*)cs_v, *p_tf=(float*)tf_v, *p_h1=(float*)h1_v, *p_h2=(float*)h2_v;
  float *p_w1g=(float*)w1gp_v;

  const long SBIG = (long)NP*NP;
  const long SXS  = (long)128*NP;

  // weight planes (deterministic each call)
  to_planes_kernel<<<(1024*512+255)/256, 256>>>(Wf, 1024*512, 512, 512, p_wfh, p_wfl);
  to_planes_kernel<<<(512*512+255)/256, 256>>>(Wc1 + 1024, 512*512, 512, 1536, p_w1h, p_w1l);
  to_planes_kernel<<<(256*512+255)/256, 256>>>(Wc2, 256*512, 512, 512, p_w2h, p_w2l);

  // ---- knn on xyz + edgeconv1 ----
  pdist1_kernel<<<NB*NP, 256>>>(x);
  topk_kernel<<<NB*NP, 256>>>();
  zero_slots_kernel<<<128, 256>>>();
  edge_pq_kernel<<<dim3(NP/32, NB), 256>>>(x, -1, (long)3*NP, 3, We1);
  edge_gather_kernel<<<NB*NP, 64>>>(0);
  bn_finalize_kernel<<<1, 64>>>(64, (float)((long)NB*NP*KNN));
  bn_relu_kernel<<<(NB*64*NP)/256, 256>>>(1, SXS, 64, 0);

  // ---- knn on f1 (fp32 gram — preserves neighbor selection) + edgeconv2 ----
  sqnorm_kernel<<<(NB*NP)/256, 256>>>();
  gemm_kernel<1, true><<<dim3(16, 32, NB), 256>>>(NP, 64,
      nullptr, 1, NP, SXS, 1, NP, SXS,
      nullptr, 0, NP, SBIG, nullptr, 12, NP, -1, 0);
  topk_kernel<<<NB*NP, 256>>>();
  zero_slots_kernel<<<128, 256>>>();
  edge_pq_kernel<<<dim3(NP/32, NB), 256>>>(nullptr, 1, SXS, 64, We2);
  edge_gather_kernel<<<NB*NP, 64>>>(64);
  bn_finalize_kernel<<<1, 64>>>(64, (float)((long)NB*NP*KNN));
  bn_relu_kernel<<<(NB*64*NP)/256, 256>>>(1, SXS, 64, 64);

  // xs planes (layer-0 input)
  to_planes_kernel<<<((long)NB*128*NP+255)/256, 256>>>(p_xs, (long)NB*128*NP, NP, NP, p_xsh, p_xsl);

  // ---- 4 SA layers ----
  for (int i = 0; i < 4; i++){
    qk_kernel<<<dim3(NP/32, NB), 256>>>(Wq + (long)i*32*128, Wk + (long)i*32*128,
                                        p_qh, p_ql, p_kh, p_kl);
    // energy = qT @ k  (M=2048, K=32)
    mma_gemm<0, false><<<dim3(16, 16, NB), 256>>>(NP, 32,
        p_qh, p_ql, 32, (long)NP*32,
        p_kh, p_kl, (long)32*NP,
        p_big, NP, SBIG,
        nullptr, nullptr, nullptr, 0, nullptr, 0);
    softmax_kernel<<<NB*NP, 256>>>(p_ah, p_al);
    colsum_kernel<<<dim3(NP/256, NB), 256>>>(p_ah, p_al);
    // y = Wt @ xs  (also emit y planes)
    to_planes_kernel<<<(128*128+255)/256, 256>>>(Wt + (long)i*128*128, 128*128, 128, 128, p_wth, p_wtl);
    mma_gemm<0, true><<<dim3(16, 1, NB), 256>>>(128, 128,
        p_wth, p_wtl, 128, 0,
        p_xsh, p_xsl, SXS,
        p_t, NP, SXS,
        p_yh, p_yl, nullptr, 0, nullptr, 0);
    zero_slots_kernel<<<128, 256>>>();
    // t = y - (y @ attn) * cs  (+ BN stats)
    mma_gemm<6, false><<<dim3(16, 1, NB), 256>>>(128, NP,
        p_yh, p_yl, NP, SXS,
        p_ah, p_al, SBIG,
        p_d, NP, SXS,
        nullptr, nullptr, p_t, SXS, p_cs, NP);
    bn_finalize_kernel<<<1, 128>>>(128, (float)(NB*NP));
    residual_kernel<<<(NB*128*NP)/256, 256>>>(i, p_xsh, p_xsl, p_ch, p_cl);
  }

  // ---- fuse + global max ----
  zero_slots_kernel<<<128, 256>>>();
  mma_gemm<3, false><<<dim3(16, 8, NB), 256>>>(1024, 512,
      p_wfh, p_wfl, 512, 0,
      p_ch, p_cl, (long)512*NP,
      p_tf, NP, (long)1024*NP,
      nullptr, nullptr, nullptr, 0, nullptr, 0);
  bn_finalize_kernel<<<8, 128>>>(1024, (float)(NB*NP));
  gmax_kernel<<<NB*1024, 128>>>();
  w1g_kernel<<<64, 256>>>(Wc1);

  // ---- head ----
  zero_slots_kernel<<<128, 256>>>();
  mma_gemm<4, false><<<dim3(16, 4, NB), 256>>>(512, 512,
      p_w1h, p_w1l, 512, 0,
      p_ch, p_cl, (long)512*NP,
      p_h1, NP, (long)512*NP,
      nullptr, nullptr, p_w1g, 512, nullptr, 0);
  bn_finalize_kernel<<<4, 128>>>(512, (float)(NB*NP));
  bn_relu_planes_kernel<<<((long)NB*512*NP)/256, 256>>>(p_h1, 512, p_h1h, p_h1l);

  zero_slots_kernel<<<128, 256>>>();
  mma_gemm<3, false><<<dim3(16, 2, NB), 256>>>(256, 512,
      p_w2h, p_w2l, 512, 0,
      p_h1h, p_h1l, (long)512*NP,
      p_h2, NP, (long)256*NP,
      nullptr, nullptr, nullptr, 0, nullptr, 0);
  bn_finalize_kernel<<<2, 128>>>(256, (float)(NB*NP));
  bn_relu_kernel<<<(NB*256*NP)/256, 256>>>(11, (long)256*NP, 256, 0);

  gemm_kernel<5, false><<<dim3(16, 1, NB), 256>>>(13, 256,
      Wc3, -1, 256, 0, 11, NP, (long)256*NP,
      out, -1, NP, (long)13*NP, bc3, -1, 0, -1, 0);
}

// round 12
// speedup vs baseline: 1.5160x; 1.2277x over previous
#include <cuda_runtime.h>
#include <cuda_bf16.h>
#include <cstdint>

#define NB 8
#define NP 2048
#define KNN 32
#define NSLOT 32
#define EPSBN 1e-5f
#define NEG_INF -3.402823466e38f

typedef __nv_bfloat16 bf16;

// ----------------- static device scratch (no runtime allocation) -----------------
__device__ float g_big[(size_t)NB*NP*NP];     // pdist (fp32)
__device__ bf16  g_ah[(size_t)NB*NP*NP];      // energy -> attn (bf16, in-place softmax)
__device__ int   g_idx[(size_t)NB*NP*KNN];
__device__ float g_xx[NB*NP];
__device__ float g_xs[(size_t)NB*128*NP];     // running SA features (fp32)
__device__ bf16  g_xsh[(size_t)NB*128*NP];
__device__ bf16  g_xsl[(size_t)NB*128*NP];
__device__ bf16  g_ch[(size_t)NB*512*NP];     // cat planes
__device__ bf16  g_cl[(size_t)NB*512*NP];
__device__ float g_pt[(size_t)NB*NP*64];
__device__ float g_qt[(size_t)NB*NP*64];
__device__ bf16  g_qh[(size_t)NB*NP*32];      // q^T planes (point-major, lda=32)
__device__ bf16  g_ql[(size_t)NB*NP*32];
__device__ bf16  g_kh[(size_t)NB*32*NP];      // k planes [32][NP]
__device__ bf16  g_kl[(size_t)NB*32*NP];
__device__ float g_d[(size_t)NB*128*NP];      // t pre-BN
__device__ float g_t[(size_t)NB*128*NP];      // y = Wt @ xs (fp32)
__device__ bf16  g_yh[(size_t)NB*128*NP];
__device__ bf16  g_yl[(size_t)NB*128*NP];
__device__ float g_cs[NB*NP];
__device__ float g_tf[(size_t)NB*1024*NP];    // fuse pre-BN
__device__ float g_h1[(size_t)NB*512*NP];
__device__ bf16  g_h1h[(size_t)NB*512*NP];    // relu(bn(h1)) planes
__device__ bf16  g_h1l[(size_t)NB*512*NP];
__device__ float g_h2[(size_t)NB*256*NP];
__device__ float g_gm[NB*1024];
__device__ float g_w1g[NB*512];
__device__ bf16  g_wfh[1024*512]; __device__ bf16 g_wfl[1024*512];
__device__ bf16  g_w1h[512*512];  __device__ bf16 g_w1l[512*512];
__device__ bf16  g_w2h[256*512];  __device__ bf16 g_w2l[256*512];
__device__ bf16  g_wth[128*128];  __device__ bf16 g_wtl[128*128];
__device__ float g_ssum[1024*NSLOT];
__device__ float g_ssq[1024*NSLOT];
__device__ float g_mean[1024];
__device__ float g_istd[1024];

__device__ __forceinline__ float* bsel(int s){
  switch(s){
    case 0: return g_big;  case 1: return g_xs;
    case 11: return g_h2;  case 12: return g_xx;
  }
  return nullptr;
}

// ----------------- small utility kernels -----------------
__global__ void zero_slots_kernel(){
  int i = blockIdx.x*256 + threadIdx.x;
  if (i < 1024*NSLOT){ g_ssum[i] = 0.f; g_ssq[i] = 0.f; }
}

__global__ void bn_finalize_kernel(int C, float count){
  int c = blockIdx.x*blockDim.x + threadIdx.x;
  if (c >= C) return;
  float s1 = 0.f, s2 = 0.f;
  for (int s = 0; s < NSLOT; s++){ s1 += g_ssum[c*NSLOT+s]; s2 += g_ssq[c*NSLOT+s]; }
  float m = s1 / count;
  float var = s2 / count - m*m;
  g_mean[c] = m;
  g_istd[c] = rsqrtf(fmaxf(var, 0.f) + EPSBN);
}

__global__ void bn_relu_kernel(int dSel, long bstride, int C, int choff){
  float* data = bsel(dSel);
  long i = (long)blockIdx.x*blockDim.x + threadIdx.x;
  long tot = (long)NB*C*NP;
  if (i >= tot) return;
  int n = (int)(i % NP); long t = i / NP;
  int c = (int)(t % C);  int b = (int)(t / C);
  float* p = data + (long)b*bstride + (long)(choff+c)*NP + n;
  float v = (*p - g_mean[c]) * g_istd[c];
  *p = v > 0.f ? v : 0.f;
}

// relu(bn(src)) -> bf16 planes only (h1 path); layout [b][C][NP] packed
__global__ void bn_relu_planes_kernel(const float* __restrict__ src, int C,
                                      bf16* __restrict__ H, bf16* __restrict__ L){
  long i = (long)blockIdx.x*blockDim.x + threadIdx.x;
  long tot = (long)NB*C*NP;
  if (i >= tot) return;
  int c = (int)((i / NP) % C);
  float v = (src[i] - g_mean[c]) * g_istd[c];
  v = v > 0.f ? v : 0.f;
  bf16 hi = __float2bfloat16(v);
  H[i] = hi; L[i] = __float2bfloat16(v - __bfloat162float(hi));
}

// generic fp32 -> split planes (packed [total] with source ld)
__global__ void to_planes_kernel(const float* __restrict__ src, long total, int cols, int ld,
                                 bf16* __restrict__ H, bf16* __restrict__ L){
  long i = (long)blockIdx.x*256 + threadIdx.x;
  if (i >= total) return;
  long r = i / cols; int c = (int)(i % cols);
  float v = src[r*(long)ld + c];
  bf16 hi = __float2bfloat16(v);
  H[i] = hi; L[i] = __float2bfloat16(v - __bfloat162float(hi));
}

// ----------------- knn -----------------
__global__ void pdist1_kernel(const float* __restrict__ x){
  int row = blockIdx.x;
  int b = row / NP, n = row % NP;
  const float* xb = x + (long)b*3*NP;
  float cx = xb[n], cy = xb[NP+n], cz = xb[2*NP+n];
  float* out = g_big + (long)row*NP;
  for (int m = threadIdx.x; m < NP; m += blockDim.x){
    float dx = xb[m]-cx, dy = xb[NP+m]-cy, dz = xb[2*NP+m]-cz;
    out[m] = -(dx*dx + dy*dy + dz*dz);
  }
}

__global__ void topk_kernel(){
  int row = blockIdx.x;
  const float* src = g_big + (long)row*NP;
  int tid = threadIdx.x;
  float v[8];
  #pragma unroll
  for (int i = 0; i < 8; i++) v[i] = src[tid + i*256];
  __shared__ float swv[8]; __shared__ int swi[8]; __shared__ int sbi;
  int lane = tid & 31, wid = tid >> 5;
  int* idxout = g_idx + (long)row*KNN;
  for (int it = 0; it < KNN; it++){
    float bv = v[0]; int bs = 0;
    #pragma unroll
    for (int i = 1; i < 8; i++) if (v[i] > bv){ bv = v[i]; bs = i; }
    int bidx = tid + bs*256;
    #pragma unroll
    for (int off = 16; off; off >>= 1){
      float ov = __shfl_down_sync(0xffffffffu, bv, off);
      int   oi = __shfl_down_sync(0xffffffffu, bidx, off);
      if (ov > bv || (ov == bv && oi < bidx)){ bv = ov; bidx = oi; }
    }
    if (lane == 0){ swv[wid] = bv; swi[wid] = bidx; }
    __syncthreads();
    if (tid == 0){
      float mv = swv[0]; int mi = swi[0];
      #pragma unroll
      for (int w = 1; w < 8; w++)
        if (swv[w] > mv || (swv[w] == mv && swi[w] < mi)){ mv = swv[w]; mi = swi[w]; }
      sbi = mi; idxout[it] = mi;
    }
    __syncthreads();
    int w = sbi;
    if ((w & 255) == tid) v[w >> 8] = NEG_INF;
  }
}

// ----------------- edge conv -----------------
__global__ void edge_pq_kernel(const float* __restrict__ fext, int fSel, long fbstride,
                               int C, const float* __restrict__ W){
  const float* f = (fSel >= 0) ? bsel(fSel) : fext;
  int b = blockIdx.y;
  int n0 = blockIdx.x*32;
  const float* fb = f + (long)b*fbstride;
  __shared__ float sf[64][32];
  int nl = threadIdx.x & 31, og = threadIdx.x >> 5;
  for (int c = og; c < C; c += 8) sf[c][nl] = fb[(long)c*NP + n0 + nl];
  __syncthreads();
  #pragma unroll
  for (int j = 0; j < 8; j++){
    int o = og*8 + j;
    const float* w = W + (long)o*2*C;
    float ap = 0.f, aq = 0.f;
    for (int c = 0; c < C; c++){
      float fv = sf[c][nl];
      ap += w[c]*fv;
      aq += (w[C+c]-w[c])*fv;
    }
    long off = ((long)(b*NP + n0 + nl))*64 + o;
    g_pt[off] = ap; g_qt[off] = aq;
  }
}

__global__ void edge_gather_kernel(int chbase){
  int row = blockIdx.x; int b = row / NP, n = row % NP;
  int o = threadIdx.x;
  __shared__ int sidx[KNN];
  if (o < KNN) sidx[o] = g_idx[(long)row*KNN + o];
  __syncthreads();
  float q = g_qt[(long)row*64 + o];
  float mx = NEG_INF, s1 = 0.f, s2 = 0.f;
  const float* pb = g_pt + (long)b*NP*64;
  #pragma unroll 4
  for (int k = 0; k < KNN; k++){
    float v = pb[(long)sidx[k]*64 + o] + q;
    mx = fmaxf(mx, v); s1 += v; s2 += v*v;
  }
  g_xs[((long)b*128 + chbase + o)*NP + n] = mx;
  int slot = row & (NSLOT-1);
  atomicAdd(&g_ssum[o*NSLOT + slot], s1);
  atomicAdd(&g_ssq[o*NSLOT + slot], s2);
}

__global__ void sqnorm_kernel(){
  int i = blockIdx.x*blockDim.x + threadIdx.x;
  if (i >= NB*NP) return;
  int b = i / NP, n = i % NP;
  const float* f = g_xs + (long)b*128*NP + n;
  float s = 0.f;
  #pragma unroll 8
  for (int c = 0; c < 64; c++){ float v = f[(long)c*NP]; s += v*v; }
  g_xx[i] = s;
}

// ----------------- SA layer helpers -----------------
__global__ void qk_kernel(const float* __restrict__ Wq, const float* __restrict__ Wk,
                          bf16* __restrict__ qTh, bf16* __restrict__ qTl,
                          bf16* __restrict__ kh, bf16* __restrict__ kl){
  int b = blockIdx.y, n0 = blockIdx.x*32;
  __shared__ float sf[128][32];
  int nl = threadIdx.x & 31, og = threadIdx.x >> 5;
  const float* xb = g_xs + (long)b*128*NP;
  for (int c = og; c < 128; c += 8) sf[c][nl] = xb[(long)c*NP + n0 + nl];
  __syncthreads();
  #pragma unroll
  for (int j = 0; j < 4; j++){
    int qi = og*4 + j;
    const float* wq = Wq + qi*128;
    const float* wk = Wk + qi*128;
    float aq = 0.f, ak = 0.f;
    for (int c = 0; c < 128; c++){
      float fv = sf[c][nl];
      aq += wq[c]*fv; ak += wk[c]*fv;
    }
    bf16 qh = __float2bfloat16(aq);
    bf16 ql = __float2bfloat16(aq - __bfloat162float(qh));
    bf16 kh2 = __float2bfloat16(ak);
    bf16 kl2 = __float2bfloat16(ak - __bfloat162float(kh2));
    long qoff = ((long)b*NP + n0 + nl)*32 + qi;
    qTh[qoff] = qh; qTl[qoff] = ql;
    long koff = ((long)b*32 + qi)*NP + n0 + nl;
    kh[koff] = kh2; kl[koff] = kl2;
  }
}

// softmax IN PLACE on bf16 energy rows -> bf16 attn rows
__global__ void softmax_kernel(bf16* __restrict__ ah){
  long row = blockIdx.x;
  bf16* p = ah + row*(long)NP;
  int tid = threadIdx.x;
  int lane = tid & 31, wid = tid >> 5;
  __shared__ float sred[8];
  __shared__ float sres;
  float v[8];
  #pragma unroll
  for (int i = 0; i < 8; i++) v[i] = __bfloat162float(p[tid + i*256]);
  float m = v[0];
  #pragma unroll
  for (int i = 1; i < 8; i++) m = fmaxf(m, v[i]);
  #pragma unroll
  for (int off = 16; off; off >>= 1) m = fmaxf(m, __shfl_xor_sync(0xffffffffu, m, off));
  if (lane == 0) sred[wid] = m;
  __syncthreads();
  if (tid == 0){
    float t = sred[0];
    #pragma unroll
    for (int w = 1; w < 8; w++) t = fmaxf(t, sred[w]);
    sres = t;
  }
  __syncthreads();
  float bmax = sres;
  float s = 0.f;
  #pragma unroll
  for (int i = 0; i < 8; i++){ v[i] = __expf(v[i] - bmax); s += v[i]; }
  #pragma unroll
  for (int off = 16; off; off >>= 1) s += __shfl_xor_sync(0xffffffffu, s, off);
  __syncthreads();
  if (lane == 0) sred[wid] = s;
  __syncthreads();
  if (tid == 0){
    float t = 0.f;
    #pragma unroll
    for (int w = 0; w < 8; w++) t += sred[w];
    sres = t;
  }
  __syncthreads();
  float inv = 1.f / sres;
  #pragma unroll
  for (int i = 0; i < 8; i++)
    p[tid + i*256] = __float2bfloat16(v[i]*inv);
}

__global__ void colsum_kernel(const bf16* __restrict__ ah){
  int b = blockIdx.y;
  int m = blockIdx.x*256 + threadIdx.x;
  const bf16* A = ah + (long)b*NP*NP + m;
  float s = 0.f;
  for (int n = 0; n < NP; n++)
    s += __bfloat162float(A[(long)n*NP]);
  g_cs[b*NP + m] = 1.f / (1e-6f + s);
}

// residual: xs += relu(bn(t)); write xs planes + cat plane slice
__global__ void residual_kernel(int layer,
                                bf16* __restrict__ xsh, bf16* __restrict__ xsl,
                                bf16* __restrict__ ch, bf16* __restrict__ cl){
  long i = (long)blockIdx.x*blockDim.x + threadIdx.x;
  long tot = (long)NB*128*NP;
  if (i >= tot) return;
  int n = (int)(i % NP); long t = i / NP;
  int c = (int)(t % 128); int b = (int)(t / 128);
  long xi = ((long)b*128 + c)*NP + n;
  float tv = g_d[xi];
  float r = (tv - g_mean[c]) * g_istd[c];
  r = r > 0.f ? r : 0.f;
  float v = g_xs[xi] + r;
  g_xs[xi] = v;
  bf16 hi = __float2bfloat16(v);
  bf16 lo = __float2bfloat16(v - __bfloat162float(hi));
  xsh[xi] = hi; xsl[xi] = lo;
  long ci = ((long)b*512 + layer*128 + c)*NP + n;
  ch[ci] = hi; cl[ci] = lo;
}

// ----------------- fuse / head helpers -----------------
__global__ void gmax_kernel(){
  int row = blockIdx.x;
  int o = row & 1023;
  const float* p = g_tf + (long)row*NP;
  float m = NEG_INF;
  for (int n = threadIdx.x; n < NP; n += 128) m = fmaxf(m, p[n]);
  #pragma unroll
  for (int off = 16; off; off >>= 1) m = fmaxf(m, __shfl_xor_sync(0xffffffffu, m, off));
  __shared__ float sw[4];
  int lane = threadIdx.x & 31, wid = threadIdx.x >> 5;
  if (lane == 0) sw[wid] = m;
  __syncthreads();
  if (threadIdx.x == 0){
    float mm = fmaxf(fmaxf(sw[0], sw[1]), fmaxf(sw[2], sw[3]));
    float v = (mm - g_mean[o]) * g_istd[o];
    g_gm[row] = v > 0.f ? v : 0.f;
  }
}

__global__ void w1g_kernel(const float* __restrict__ Wc1){
  int o = blockIdx.x*8 + (threadIdx.x >> 5);
  int lane = threadIdx.x & 31;
  const float* w = Wc1 + (long)o*1536;
  float acc[NB];
  #pragma unroll
  for (int b = 0; b < NB; b++) acc[b] = 0.f;
  for (int c = lane; c < 1024; c += 32){
    float wv = w[c];
    #pragma unroll
    for (int b = 0; b < NB; b++) acc[b] += wv * g_gm[b*1024 + c];
  }
  #pragma unroll
  for (int b = 0; b < NB; b++){
    #pragma unroll
    for (int off = 16; off; off >>= 1) acc[b] += __shfl_xor_sync(0xffffffffu, acc[b], off);
  }
  if (lane == 0){
    #pragma unroll
    for (int b = 0; b < NB; b++) g_w1g[b*512 + o] = acc[b];
  }
}

// ----------------- tensor-core bf16-split GEMM -----------------
__device__ __forceinline__ uint32_t smem_u32(const void* p){
  return (uint32_t)__cvta_generic_to_shared(p);
}
__device__ __forceinline__ void ldm_x4(uint32_t a, uint32_t &r0, uint32_t &r1, uint32_t &r2, uint32_t &r3){
  asm volatile("ldmatrix.sync.aligned.m8n8.x4.shared.b16 {%0,%1,%2,%3}, [%4];"
    : "=r"(r0),"=r"(r1),"=r"(r2),"=r"(r3) : "r"(a));
}
__device__ __forceinline__ void ldm_x4t(uint32_t a, uint32_t &r0, uint32_t &r1, uint32_t &r2, uint32_t &r3){
  asm volatile("ldmatrix.sync.aligned.m8n8.x4.trans.shared.b16 {%0,%1,%2,%3}, [%4];"
    : "=r"(r0),"=r"(r1),"=r"(r2),"=r"(r3) : "r"(a));
}
__device__ __forceinline__ void mma16816(float* d, const uint32_t* a, const uint32_t* b){
  asm volatile("mma.sync.aligned.m16n8k16.row.col.f32.bf16.bf16.f32 "
    "{%0,%1,%2,%3}, {%4,%5,%6,%7}, {%8,%9}, {%0,%1,%2,%3};"
    : "+f"(d[0]),"+f"(d[1]),"+f"(d[2]),"+f"(d[3])
    : "r"(a[0]),"r"(a[1]),"r"(a[2]),"r"(a[3]), "r"(b[0]),"r"(b[1]));
}

// C[b](M x 2048) = A[b](M x K, hi/lo planes, lda) * B[b](K x 2048, ldb=NP)
// EPI: 0 plain, 3 stats, 4 stats+rowbias(E1[b][row]), 6 xr: v=E1[row*NP+col]-a*E2[col] +stats
// POUT: 0 = fp32 C only; 1 = fp32 C + bf16 hi/lo planes; 2 = bf16 hi plane ONLY (no C write)
// BLO: B has a lo plane (3-product split) or hi only (2 products)
template<int EPI, int POUT, bool BLO>
__global__ void __launch_bounds__(256)
mma_gemm(int M, int K,
  const bf16* __restrict__ Ah, const bf16* __restrict__ Al, int lda, long sA,
  const bf16* __restrict__ Bh, const bf16* __restrict__ Bl, long sB,
  float* __restrict__ Cc, int ldc, long sC,
  bf16* __restrict__ Ph, bf16* __restrict__ Pl,
  const float* __restrict__ E1, long se1,
  const float* __restrict__ E2, long se2)
{
  __shared__ bf16 As[2][128][40];
  __shared__ bf16 Bs[BLO ? 2 : 1][32][136];
  int bb = blockIdx.z;
  const bf16* Ap[2] = {Ah + (long)bb*sA, Al + (long)bb*sA};
  const bf16* Bp0 = Bh + (long)bb*sB;
  const bf16* Bp1 = BLO ? (Bl + (long)bb*sB) : nullptr;
  float* C = Cc + (long)bb*sC;
  const float* e1 = nullptr; const float* e2 = nullptr;
  if (EPI == 4 || EPI == 6) e1 = E1 + (long)bb*se1;
  if (EPI == 6) e2 = E2 + (long)bb*se2;

  int tm = blockIdx.y*128, tn = blockIdx.x*128;
  int tid = threadIdx.x, lane = tid & 31, wid = tid >> 5;
  int wm = wid >> 2, wn = wid & 3;

  float acc[4][4][4];
  #pragma unroll
  for (int i = 0; i < 4; i++)
    #pragma unroll
    for (int j = 0; j < 4; j++)
      #pragma unroll
      for (int u = 0; u < 4; u++) acc[i][j][u] = 0.f;

  int fr = lane & 15, fs = lane >> 4;  // ldmatrix lane row / half-select

  for (int k0 = 0; k0 < K; k0 += 32){
    #pragma unroll
    for (int l = 0; l < 4; l++){
      int li = tid + l*256;
      int p = li >> 9, s = li & 511;
      int r = s >> 2, seg = (s & 3)*8;
      uint4 v = *(const uint4*)&Ap[p][(long)(tm + r)*lda + k0 + seg];
      *(uint4*)&As[p][r][seg] = v;
    }
    {
      constexpr int NBL = BLO ? 4 : 2;
      #pragma unroll
      for (int l = 0; l < NBL; l++){
        int li = tid + l*256;
        int p = li >> 9, s = li & 511;
        int kk = s >> 4, seg = (s & 15)*8;
        const bf16* src = (p == 0) ? Bp0 : Bp1;
        uint4 v = *(const uint4*)&src[(long)(k0 + kk)*NP + tn + seg];
        *(uint4*)&Bs[p][kk][seg] = v;
      }
    }
    __syncthreads();
    #pragma unroll
    for (int ks = 0; ks < 2; ks++){
      uint32_t aF[2][4][4], bF[2][4][2];
      #pragma unroll
      for (int p = 0; p < 2; p++){
        #pragma unroll
        for (int i = 0; i < 4; i++){
          uint32_t ad = smem_u32(&As[p][wm*64 + i*16 + fr][ks*16 + fs*8]);
          ldm_x4(ad, aF[p][i][0], aF[p][i][1], aF[p][i][2], aF[p][i][3]);
        }
      }
      constexpr int NBP = BLO ? 2 : 1;
      #pragma unroll
      for (int p = 0; p < NBP; p++){
        #pragma unroll
        for (int j2 = 0; j2 < 2; j2++){
          uint32_t ad = smem_u32(&Bs[p][ks*16 + fr][wn*32 + j2*16 + fs*8]);
          ldm_x4t(ad, bF[p][j2*2][0], bF[p][j2*2][1], bF[p][j2*2+1][0], bF[p][j2*2+1][1]);
        }
      }
      #pragma unroll
      for (int i = 0; i < 4; i++)
        #pragma unroll
        for (int j = 0; j < 4; j++){
          mma16816(acc[i][j], aF[0][i], bF[0][j]);
          if (BLO) mma16816(acc[i][j], aF[0][i], bF[1][j]);
          mma16816(acc[i][j], aF[1][i], bF[0][j]);
        }
    }
    __syncthreads();
  }

  int gr = lane >> 2, cp = (lane & 3)*2;
  int slot = (blockIdx.x + blockIdx.z*5) & (NSLOT-1);
  float s1[4][2], s2[4][2];
  #pragma unroll
  for (int i = 0; i < 4; i++){ s1[i][0]=s1[i][1]=0.f; s2[i][0]=s2[i][1]=0.f; }

  #pragma unroll
  for (int i = 0; i < 4; i++){
    #pragma unroll
    for (int h = 0; h < 2; h++){
      int row = tm + wm*64 + i*16 + gr + h*8;
      float rowbias = (EPI == 4) ? e1[row] : 0.f;
      #pragma unroll
      for (int j = 0; j < 4; j++){
        int col = tn + wn*32 + j*8 + cp;
        #pragma unroll
        for (int u = 0; u < 2; u++){
          float v = acc[i][j][h*2 + u];
          int cc = col + u;
          if (EPI == 6) v = e1[(long)row*NP + cc] - v*e2[cc];
          else v += rowbias;
          if (POUT != 2) C[(long)row*ldc + cc] = v;
          if (POUT == 1){
            bf16 hi = __float2bfloat16(v);
            long po = (long)bb*sC + (long)row*ldc + cc;
            Ph[po] = hi; Pl[po] = __float2bfloat16(v - __bfloat162float(hi));
          } else if (POUT == 2){
            long po = (long)bb*sC + (long)row*ldc + cc;
            Ph[po] = __float2bfloat16(v);
          }
          if (EPI == 3 || EPI == 4 || EPI == 6){ s1[i][h] += v; s2[i][h] += v*v; }
        }
      }
    }
  }
  if (EPI == 3 || EPI == 4 || EPI == 6){
    #pragma unroll
    for (int i = 0; i < 4; i++)
      #pragma unroll
      for (int h = 0; h < 2; h++){
        float a1 = s1[i][h], a2 = s2[i][h];
        a1 += __shfl_xor_sync(0xffffffffu, a1, 1); a2 += __shfl_xor_sync(0xffffffffu, a2, 1);
        a1 += __shfl_xor_sync(0xffffffffu, a1, 2); a2 += __shfl_xor_sync(0xffffffffu, a2, 2);
        if ((lane & 3) == 0){
          int row = tm + wm*64 + i*16 + gr + h*8;
          atomicAdd(&g_ssum[row*NSLOT + slot], a1);
          atomicAdd(&g_ssq [row*NSLOT + slot], a2);
        }
      }
  }
}

// ----------------- fp32 tiled SGEMM (pdist2 gram + final Wc3 only) -----------------
template<int EPI, bool TRANSA>
__global__ void __launch_bounds__(256)
gemm_kernel(int M, int K,
  const float* __restrict__ Aext, int aSel, int lda, long sA,
  int bSel, int ldb, long sB,
  float* __restrict__ Cext, int cSel, int ldc, long sC,
  const float* __restrict__ e1ext, int e1Sel, long se1,
  int e2Sel, long se2)
{
  int bb = blockIdx.z;
  const float* A = ((aSel >= 0) ? bsel(aSel) : Aext) + (long)bb*sA;
  const float* B = bsel(bSel) + (long)bb*sB;
  float* C = ((cSel >= 0) ? bsel(cSel) : Cext) + (long)bb*sC;
  const float* E1 = nullptr;
  if (EPI == 1 || EPI == 5)
    E1 = ((e1Sel >= 0) ? bsel(e1Sel) : e1ext) + (long)bb*se1;

  int tm = blockIdx.y*64, tn = blockIdx.x*128;
  __shared__ float As[32][68];
  __shared__ float Bs[32][128];
  int tid = threadIdx.x;
  int tx = tid & 15, ty = tid >> 4;
  float acc[4][8] = {};

  for (int k0 = 0; k0 < K; k0 += 32){
    if (TRANSA){
      int kk = tid >> 4, mm = (tid & 15)*4;
      *(float4*)&As[kk   ][mm] = *(const float4*)&A[(long)(k0+kk   )*lda + tm + mm];
      *(float4*)&As[kk+16][mm] = *(const float4*)&A[(long)(k0+kk+16)*lda + tm + mm];
    } else {
      int rl = tid >> 2, kk = (tid & 3)*8;
      int row = tm + rl;
      float4 a0 = make_float4(0.f,0.f,0.f,0.f), a1 = a0;
      if (row < M){
        a0 = *(const float4*)&A[(long)row*lda + k0 + kk];
        a1 = *(const float4*)&A[(long)row*lda + k0 + kk + 4];
      }
      As[kk  ][rl] = a0.x; As[kk+1][rl] = a0.y; As[kk+2][rl] = a0.z; As[kk+3][rl] = a0.w;
      As[kk+4][rl] = a1.x; As[kk+5][rl] = a1.y; As[kk+6][rl] = a1.z; As[kk+7][rl] = a1.w;
    }
    {
      int kb = tid >> 4, nn = (tid & 15)*4;
      *(float4*)&Bs[kb   ][nn   ] = *(const float4*)&B[(long)(k0+kb   )*ldb + tn + nn];
      *(float4*)&Bs[kb   ][nn+64] = *(const float4*)&B[(long)(k0+kb   )*ldb + tn + nn + 64];
      *(float4*)&Bs[kb+16][nn   ] = *(const float4*)&B[(long)(k0+kb+16)*ldb + tn + nn];
      *(float4*)&Bs[kb+16][nn+64] = *(const float4*)&B[(long)(k0+kb+16)*ldb + tn + nn + 64];
    }
    __syncthreads();
    #pragma unroll
    for (int kk = 0; kk < 32; kk++){
      float4 a4 = *(float4*)&As[kk][ty*4];
      float4 b0 = *(float4*)&Bs[kk][tx*4];
      float4 b1 = *(float4*)&Bs[kk][64 + tx*4];
      float ar[4] = {a4.x, a4.y, a4.z, a4.w};
      float br[8] = {b0.x, b0.y, b0.z, b0.w, b1.x, b1.y, b1.z, b1.w};
      #pragma unroll
      for (int i = 0; i < 4; i++)
        #pragma unroll
        for (int j = 0; j < 8; j++)
          acc[i][j] += ar[i]*br[j];
    }
    __syncthreads();
  }

  int c0 = tn + tx*4, c1 = tn + 64 + tx*4;
  #pragma unroll
  for (int i = 0; i < 4; i++){
    int row = tm + ty*4 + i;
    bool ok = row < M;
    float bias = 0.f;
    if (EPI == 5 && ok) bias = E1[row];
    float out[8];
    #pragma unroll
    for (int j = 0; j < 8; j++){
      int col = (j < 4) ? (c0 + j) : (c1 + j - 4);
      float v = acc[i][j];
      if (EPI == 1) v = 2.f*v - (ok ? E1[row] : 0.f) - E1[col];
      else          v += bias;
      out[j] = v;
    }
    if (ok){
      *(float4*)&C[(long)row*ldc + c0] = make_float4(out[0],out[1],out[2],out[3]);
      *(float4*)&C[(long)row*ldc + c1] = make_float4(out[4],out[5],out[6],out[7]);
    }
  }
}

// ----------------- host orchestration -----------------
#define SYMADDR(var, sym) void* var##_v; cudaGetSymbolAddress(&var##_v, sym);
extern "C" void kernel_launch(void* const* d_in, const int* in_sizes, int n_in,
                              void* d_out, int out_size) {
  (void)in_sizes; (void)n_in; (void)out_size;
  const float* x   = (const float*)d_in[0];
  const float* We1 = (const float*)d_in[1];
  const float* We2 = (const float*)d_in[3];
  const float* Wq  = (const float*)d_in[5];
  const float* Wk  = (const float*)d_in[6];
  const float* Wt  = (const float*)d_in[7];
  const float* Wf  = (const float*)d_in[9];
  const float* Wc1 = (const float*)d_in[11];
  const float* Wc2 = (const float*)d_in[13];
  const float* Wc3 = (const float*)d_in[15];
  const float* bc3 = (const float*)d_in[16];
  float* out = (float*)d_out;

  SYMADDR(ah, g_ah)
  SYMADDR(xsh, g_xsh) SYMADDR(xsl, g_xsl)
  SYMADDR(ch, g_ch)   SYMADDR(cl, g_cl)
  SYMADDR(qh, g_qh)   SYMADDR(ql, g_ql)
  SYMADDR(kh, g_kh)   SYMADDR(kl, g_kl)
  SYMADDR(yh, g_yh)   SYMADDR(yl, g_yl)
  SYMADDR(h1h, g_h1h) SYMADDR(h1l, g_h1l)
  SYMADDR(wfh, g_wfh) SYMADDR(wfl, g_wfl)
  SYMADDR(w1h, g_w1h) SYMADDR(w1l, g_w1l)
  SYMADDR(w2h, g_w2h) SYMADDR(w2l, g_w2l)
  SYMADDR(wth, g_wth) SYMADDR(wtl, g_wtl)
  SYMADDR(xs, g_xs)   SYMADDR(big, g_big)
  SYMADDR(tb, g_t)    SYMADDR(db, g_d)
  SYMADDR(cs, g_cs)   SYMADDR(tf, g_tf)
  SYMADDR(h1, g_h1)   SYMADDR(h2, g_h2)
  SYMADDR(w1gp, g_w1g)
  bf16 *p_ah=(bf16*)ah_v, *p_xsh=(bf16*)xsh_v, *p_xsl=(bf16*)xsl_v;
  bf16 *p_ch=(bf16*)ch_v, *p_cl=(bf16*)cl_v, *p_qh=(bf16*)qh_v, *p_ql=(bf16*)ql_v;
  bf16 *p_kh=(bf16*)kh_v, *p_kl=(bf16*)kl_v;
  bf16 *p_yh=(bf16*)yh_v, *p_yl=(bf16*)yl_v, *p_h1h=(bf16*)h1h_v, *p_h1l=(bf16*)h1l_v;
  bf16 *p_wfh=(bf16*)wfh_v, *p_wfl=(bf16*)wfl_v, *p_w1h=(bf16*)w1h_v, *p_w1l=(bf16*)w1l_v;
  bf16 *p_w2h=(bf16*)w2h_v, *p_w2l=(bf16*)w2l_v, *p_wth=(bf16*)wth_v, *p_wtl=(bf16*)wtl_v;
  float *p_xs=(float*)xs_v, *p_big=(float*)big_v, *p_t=(float*)tb_v, *p_d=(float*)db_v;
  float *p_cs=(float*)cs_v, *p_tf=(float*)tf_v, *p_h1=(float*)h1_v, *p_h2=(float*)h2_v;
  float *p_w1g=(float*)w1gp_v;

  const long SBIG = (long)NP*NP;
  const long SXS  = (long)128*NP;

  // weight planes (deterministic each call)
  to_planes_kernel<<<(1024*512+255)/256, 256>>>(Wf, 1024*512, 512, 512, p_wfh, p_wfl);
  to_planes_kernel<<<(512*512+255)/256, 256>>>(Wc1 + 1024, 512*512, 512, 1536, p_w1h, p_w1l);
  to_planes_kernel<<<(256*512+255)/256, 256>>>(Wc2, 256*512, 512, 512, p_w2h, p_w2l);

  // ---- knn on xyz + edgeconv1 ----
  pdist1_kernel<<<NB*NP, 256>>>(x);
  topk_kernel<<<NB*NP, 256>>>();
  zero_slots_kernel<<<128, 256>>>();
  edge_pq_kernel<<<dim3(NP/32, NB), 256>>>(x, -1, (long)3*NP, 3, We1);
  edge_gather_kernel<<<NB*NP, 64>>>(0);
  bn_finalize_kernel<<<1, 64>>>(64, (float)((long)NB*NP*KNN));
  bn_relu_kernel<<<(NB*64*NP)/256, 256>>>(1, SXS, 64, 0);

  // ---- knn on f1 (fp32 gram — preserves neighbor selection) + edgeconv2 ----
  sqnorm_kernel<<<(NB*NP)/256, 256>>>();
  gemm_kernel<1, true><<<dim3(16, 32, NB), 256>>>(NP, 64,
      nullptr, 1, NP, SXS, 1, NP, SXS,
      nullptr, 0, NP, SBIG, nullptr, 12, NP, -1, 0);
  topk_kernel<<<NB*NP, 256>>>();
  zero_slots_kernel<<<128, 256>>>();
  edge_pq_kernel<<<dim3(NP/32, NB), 256>>>(nullptr, 1, SXS, 64, We2);
  edge_gather_kernel<<<NB*NP, 64>>>(64);
  bn_finalize_kernel<<<1, 64>>>(64, (float)((long)NB*NP*KNN));
  bn_relu_kernel<<<(NB*64*NP)/256, 256>>>(1, SXS, 64, 64);

  // xs planes (layer-0 input)
  to_planes_kernel<<<((long)NB*128*NP+255)/256, 256>>>(p_xs, (long)NB*128*NP, NP, NP, p_xsh, p_xsl);

  // ---- 4 SA layers ----
  for (int i = 0; i < 4; i++){
    qk_kernel<<<dim3(NP/32, NB), 256>>>(Wq + (long)i*32*128, Wk + (long)i*32*128,
                                        p_qh, p_ql, p_kh, p_kl);
    // energy = qT @ k  (M=2048, K=32) -> bf16 hi plane only
    mma_gemm<0, 2, true><<<dim3(16, 16, NB), 256>>>(NP, 32,
        p_qh, p_ql, 32, (long)NP*32,
        p_kh, p_kl, (long)32*NP,
        p_big, NP, SBIG,
        p_ah, nullptr, nullptr, 0, nullptr, 0);
    softmax_kernel<<<NB*NP, 256>>>(p_ah);
    colsum_kernel<<<dim3(NP/256, NB), 256>>>(p_ah);
    // y = Wt @ xs  (also emit y planes)
    to_planes_kernel<<<(128*128+255)/256, 256>>>(Wt + (long)i*128*128, 128*128, 128, 128, p_wth, p_wtl);
    mma_gemm<0, 1, true><<<dim3(16, 1, NB), 256>>>(128, 128,
        p_wth, p_wtl, 128, 0,
        p_xsh, p_xsl, SXS,
        p_t, NP, SXS,
        p_yh, p_yl, nullptr, 0, nullptr, 0);
    zero_slots_kernel<<<128, 256>>>();
    // t = y - (y @ attn) * cs  (+ BN stats); attn hi-only
    mma_gemm<6, 0, false><<<dim3(16, 1, NB), 256>>>(128, NP,
        p_yh, p_yl, NP, SXS,
        p_ah, p_ah, SBIG,
        p_d, NP, SXS,
        nullptr, nullptr, p_t, SXS, p_cs, NP);
    bn_finalize_kernel<<<1, 128>>>(128, (float)(NB*NP));
    residual_kernel<<<(NB*128*NP)/256, 256>>>(i, p_xsh, p_xsl, p_ch, p_cl);
  }

  // ---- fuse + global max ----
  zero_slots_kernel<<<128, 256>>>();
  mma_gemm<3, 0, true><<<dim3(16, 8, NB), 256>>>(1024, 512,
      p_wfh, p_wfl, 512, 0,
      p_ch, p_cl, (long)512*NP,
      p_tf, NP, (long)1024*NP,
      nullptr, nullptr, nullptr, 0, nullptr, 0);
  bn_finalize_kernel<<<8, 128>>>(1024, (float)(NB*NP));
  gmax_kernel<<<NB*1024, 128>>>();
  w1g_kernel<<<64, 256>>>(Wc1);

  // ---- head ----
  zero_slots_kernel<<<128, 256>>>();
  mma_gemm<4, 0, true><<<dim3(16, 4, NB), 256>>>(512, 512,
      p_w1h, p_w1l, 512, 0,
      p_ch, p_cl, (long)512*NP,
      p_h1, NP, (long)512*NP,
      nullptr, nullptr, p_w1g, 512, nullptr, 0);
  bn_finalize_kernel<<<4, 128>>>(512, (float)(NB*NP));
  bn_relu_planes_kernel<<<((long)NB*512*NP)/256, 256>>>(p_h1, 512, p_h1h, p_h1l);

  zero_slots_kernel<<<128, 256>>>();
  mma_gemm<3, 0, true><<<dim3(16, 2, NB), 256>>>(256, 512,
      p_w2h, p_w2l, 512, 0,
      p_h1h, p_h1l, (long)512*NP,
      p_h2, NP, (long)256*NP,
      nullptr, nullptr, nullptr, 0, nullptr, 0);
  bn_finalize_kernel<<<2, 128>>>(256, (float)(NB*NP));
  bn_relu_kernel<<<(NB*256*NP)/256, 256>>>(11, (long)256*NP, 256, 0);

  gemm_kernel<5, false><<<dim3(16, 1, NB), 256>>>(13, 256,
      Wc3, -1, 256, 0, 11, NP, (long)256*NP,
      out, -1, NP, (long)13*NP, bc3, -1, 0, -1, 0);
}